// round 1
// baseline (speedup 1.0000x reference)
#include <cuda_runtime.h>
#include <math.h>
#include <stdint.h>

// Problem constants
#define LSEQ 2048
#define DMODEL 4096
#define NH 32
#define NKV 8
#define HDIM 128
#define QKVN 6144            // 32*128 + 2*8*128
#define KOFF 4096            // q cols [0,4096), k cols [4096,5120), v [5120,6144)
#define VOFF 5120
#define ATT_SCALE 0.08838834764831843f  // 128^-0.5

// Scratch (no cudaMalloc allowed)
__device__ float g_qkv[(size_t)LSEQ * QKVN];   // 50.3 MB
__device__ float g_o[(size_t)LSEQ * DMODEL];   // 33.6 MB

// ---------------------------------------------------------------------------
// Tiled fp32 SGEMM: C[M,N] = A[M,K] @ B[K,N]; M%128==0, N%128==0, K%16==0
// 256 threads, 128x128x16 tiles, 8x8 microtile per thread.
// ---------------------------------------------------------------------------
__global__ __launch_bounds__(256) void sgemm128(
    const float* __restrict__ A, const float* __restrict__ B,
    float* __restrict__ C, int M, int N, int K)
{
    __shared__ float As[16][132];   // transposed A tile, padded
    __shared__ float Bs[16][128];

    const int tid = threadIdx.x;
    const int tx = tid & 15, ty = tid >> 4;
    const int bm = blockIdx.y * 128, bn = blockIdx.x * 128;
    const int row0 = ty * 8, col0 = tx * 8;

    const int a_row = tid >> 2;      // 0..63
    const int a_k4  = tid & 3;       // 0..3  (float4 index within 16-wide k)
    const int b_row = tid >> 5;      // 0..7
    const int b_c4  = tid & 31;      // 0..31 (float4 index within 128-wide n)

    float acc[8][8];
    #pragma unroll
    for (int i = 0; i < 8; i++)
        #pragma unroll
        for (int j = 0; j < 8; j++) acc[i][j] = 0.f;

    for (int kt = 0; kt < K; kt += 16) {
        #pragma unroll
        for (int r = 0; r < 2; r++) {
            int row = a_row + r * 64;
            float4 v = *(const float4*)&A[(size_t)(bm + row) * K + kt + a_k4 * 4];
            As[a_k4 * 4 + 0][row] = v.x;
            As[a_k4 * 4 + 1][row] = v.y;
            As[a_k4 * 4 + 2][row] = v.z;
            As[a_k4 * 4 + 3][row] = v.w;
        }
        #pragma unroll
        for (int r = 0; r < 2; r++) {
            int row = b_row + r * 8;
            float4 v = *(const float4*)&B[(size_t)(kt + row) * N + bn + b_c4 * 4];
            *(float4*)&Bs[row][b_c4 * 4] = v;
        }
        __syncthreads();

        #pragma unroll
        for (int k = 0; k < 16; k++) {
            float a[8], b[8];
            *(float4*)&a[0] = *(const float4*)&As[k][row0];
            *(float4*)&a[4] = *(const float4*)&As[k][row0 + 4];
            *(float4*)&b[0] = *(const float4*)&Bs[k][col0];
            *(float4*)&b[4] = *(const float4*)&Bs[k][col0 + 4];
            #pragma unroll
            for (int i = 0; i < 8; i++)
                #pragma unroll
                for (int j = 0; j < 8; j++)
                    acc[i][j] = fmaf(a[i], b[j], acc[i][j]);
        }
        __syncthreads();
    }

    #pragma unroll
    for (int i = 0; i < 8; i++) {
        size_t base = (size_t)(bm + row0 + i) * N + bn + col0;
        *(float4*)&C[base]     = make_float4(acc[i][0], acc[i][1], acc[i][2], acc[i][3]);
        *(float4*)&C[base + 4] = make_float4(acc[i][4], acc[i][5], acc[i][6], acc[i][7]);
    }
}

// ---------------------------------------------------------------------------
// In-place RoPE on q (32 heads) and k (8 heads). First 64 dims rotated:
//   j<32:   out = x[j]*cos[j] - x[j+32]*sin[j]
//   32..63: out = x[j]*cos[j] + x[j-32]*sin[j]
// grid: (L, 40); 64 threads.
// ---------------------------------------------------------------------------
__global__ void rope_kernel(const float* __restrict__ cosp,
                            const float* __restrict__ sinp)
{
    const int l = blockIdx.x;
    const int y = blockIdx.y;
    const int t = threadIdx.x;   // 0..63
    const int off = (y < NH) ? y * HDIM : KOFF + (y - NH) * HDIM;
    const size_t base = (size_t)l * QKVN + off;

    float v  = g_qkv[base + t];
    int pj   = (t < 32) ? t + 32 : t - 32;
    float pv = g_qkv[base + pj];
    float c = cosp[l * 64 + t];
    float s = sinp[l * 64 + t];
    float o = (t < 32) ? fmaf(v, c, -pv * s) : fmaf(v, c, pv * s);
    __syncthreads();
    g_qkv[base + t] = o;
}

// ---------------------------------------------------------------------------
// Flash attention (causal, GQA 32q/8kv, HD=128), fp32.
// grid: (L/64 q-tiles, 32 heads); 256 threads (16x16 logical).
// Each thread: S microtile 4x4, O microtile 4x8.
// ---------------------------------------------------------------------------
#define ATT_SMEM_FLOATS (64*128 + 128*68 + 64*128 + 64*64)
#define ATT_SMEM_BYTES  (ATT_SMEM_FLOATS * 4)

__global__ __launch_bounds__(256, 1) void attn_kernel()
{
    extern __shared__ float sm[];
    float* Qs  = sm;                   // [64][128]
    float* KsT = Qs  + 64 * 128;       // [128][68]  (K transposed, padded)
    float* Vs  = KsT + 128 * 68;       // [64][128]
    float* Ps  = Vs  + 64 * 128;       // [64][64]

    const int qt = blockIdx.x;         // q tile
    const int h  = blockIdx.y;         // head
    const int kvh = h >> 2;            // GQA: 4 q-heads per kv-head
    const int qoff = h * HDIM;
    const int koff = KOFF + kvh * HDIM;
    const int voff = VOFF + kvh * HDIM;

    const int tid = threadIdx.x;
    const int tx = tid & 15, ty = tid >> 4;
    const int r0  = ty * 4;            // 4 rows
    const int c0s = tx * 4;            // 4 cols for S
    const int c0o = tx * 8;            // 8 cols for O/V

    const int qbase = qt * 64;

    // Load Q tile
    for (int i = tid; i < 64 * 32; i += 256) {
        int row = i >> 5, c4 = i & 31;
        float4 v = *(const float4*)&g_qkv[(size_t)(qbase + row) * QKVN + qoff + c4 * 4];
        *(float4*)&Qs[row * 128 + c4 * 4] = v;
    }

    float m[4], lsum[4], acc[4][8];
    #pragma unroll
    for (int i = 0; i < 4; i++) {
        m[i] = -1e30f; lsum[i] = 0.f;
        #pragma unroll
        for (int j = 0; j < 8; j++) acc[i][j] = 0.f;
    }
    __syncthreads();

    for (int kt = 0; kt <= qt; kt++) {
        const int kb = kt * 64;
        // Load K (transposed) and V tiles
        for (int i = tid; i < 64 * 32; i += 256) {
            int row = i >> 5, c4 = i & 31;
            float4 kv = *(const float4*)&g_qkv[(size_t)(kb + row) * QKVN + koff + c4 * 4];
            int d = c4 * 4;
            KsT[(d + 0) * 68 + row] = kv.x;
            KsT[(d + 1) * 68 + row] = kv.y;
            KsT[(d + 2) * 68 + row] = kv.z;
            KsT[(d + 3) * 68 + row] = kv.w;
            float4 vv = *(const float4*)&g_qkv[(size_t)(kb + row) * QKVN + voff + c4 * 4];
            *(float4*)&Vs[row * 128 + c4 * 4] = vv;
        }
        __syncthreads();

        // S = Q @ K^T * scale
        float s[4][4];
        #pragma unroll
        for (int i = 0; i < 4; i++)
            #pragma unroll
            for (int j = 0; j < 4; j++) s[i][j] = 0.f;

        #pragma unroll 4
        for (int d = 0; d < 128; d++) {
            float q0 = Qs[(r0 + 0) * 128 + d];
            float q1 = Qs[(r0 + 1) * 128 + d];
            float q2 = Qs[(r0 + 2) * 128 + d];
            float q3 = Qs[(r0 + 3) * 128 + d];
            float4 kv = *(const float4*)&KsT[d * 68 + c0s];
            s[0][0] = fmaf(q0, kv.x, s[0][0]); s[0][1] = fmaf(q0, kv.y, s[0][1]);
            s[0][2] = fmaf(q0, kv.z, s[0][2]); s[0][3] = fmaf(q0, kv.w, s[0][3]);
            s[1][0] = fmaf(q1, kv.x, s[1][0]); s[1][1] = fmaf(q1, kv.y, s[1][1]);
            s[1][2] = fmaf(q1, kv.z, s[1][2]); s[1][3] = fmaf(q1, kv.w, s[1][3]);
            s[2][0] = fmaf(q2, kv.x, s[2][0]); s[2][1] = fmaf(q2, kv.y, s[2][1]);
            s[2][2] = fmaf(q2, kv.z, s[2][2]); s[2][3] = fmaf(q2, kv.w, s[2][3]);
            s[3][0] = fmaf(q3, kv.x, s[3][0]); s[3][1] = fmaf(q3, kv.y, s[3][1]);
            s[3][2] = fmaf(q3, kv.z, s[3][2]); s[3][3] = fmaf(q3, kv.w, s[3][3]);
        }

        // scale + causal mask
        #pragma unroll
        for (int i = 0; i < 4; i++) {
            int qr = qbase + r0 + i;
            #pragma unroll
            for (int j = 0; j < 4; j++) {
                s[i][j] *= ATT_SCALE;
                if (kb + c0s + j > qr) s[i][j] = -1e30f;
            }
        }

        // online softmax update
        #pragma unroll
        for (int i = 0; i < 4; i++) {
            float tmax = fmaxf(fmaxf(s[i][0], s[i][1]), fmaxf(s[i][2], s[i][3]));
            #pragma unroll
            for (int msk = 1; msk < 16; msk <<= 1)
                tmax = fmaxf(tmax, __shfl_xor_sync(0xffffffffu, tmax, msk, 32));
            float mn = fmaxf(m[i], tmax);
            float corr = __expf(m[i] - mn);
            m[i] = mn;

            float p0 = __expf(s[i][0] - mn);
            float p1 = __expf(s[i][1] - mn);
            float p2 = __expf(s[i][2] - mn);
            float p3 = __expf(s[i][3] - mn);
            *(float4*)&Ps[(r0 + i) * 64 + c0s] = make_float4(p0, p1, p2, p3);

            float rs = p0 + p1 + p2 + p3;
            #pragma unroll
            for (int msk = 1; msk < 16; msk <<= 1)
                rs += __shfl_xor_sync(0xffffffffu, rs, msk, 32);
            lsum[i] = lsum[i] * corr + rs;

            #pragma unroll
            for (int j = 0; j < 8; j++) acc[i][j] *= corr;
        }
        __syncwarp();

        // O += P @ V
        #pragma unroll 4
        for (int k = 0; k < 64; k++) {
            float p0 = Ps[(r0 + 0) * 64 + k];
            float p1 = Ps[(r0 + 1) * 64 + k];
            float p2 = Ps[(r0 + 2) * 64 + k];
            float p3 = Ps[(r0 + 3) * 64 + k];
            float4 v0 = *(const float4*)&Vs[k * 128 + c0o];
            float4 v1 = *(const float4*)&Vs[k * 128 + c0o + 4];
            acc[0][0] = fmaf(p0, v0.x, acc[0][0]); acc[0][1] = fmaf(p0, v0.y, acc[0][1]);
            acc[0][2] = fmaf(p0, v0.z, acc[0][2]); acc[0][3] = fmaf(p0, v0.w, acc[0][3]);
            acc[0][4] = fmaf(p0, v1.x, acc[0][4]); acc[0][5] = fmaf(p0, v1.y, acc[0][5]);
            acc[0][6] = fmaf(p0, v1.z, acc[0][6]); acc[0][7] = fmaf(p0, v1.w, acc[0][7]);
            acc[1][0] = fmaf(p1, v0.x, acc[1][0]); acc[1][1] = fmaf(p1, v0.y, acc[1][1]);
            acc[1][2] = fmaf(p1, v0.z, acc[1][2]); acc[1][3] = fmaf(p1, v0.w, acc[1][3]);
            acc[1][4] = fmaf(p1, v1.x, acc[1][4]); acc[1][5] = fmaf(p1, v1.y, acc[1][5]);
            acc[1][6] = fmaf(p1, v1.z, acc[1][6]); acc[1][7] = fmaf(p1, v1.w, acc[1][7]);
            acc[2][0] = fmaf(p2, v0.x, acc[2][0]); acc[2][1] = fmaf(p2, v0.y, acc[2][1]);
            acc[2][2] = fmaf(p2, v0.z, acc[2][2]); acc[2][3] = fmaf(p2, v0.w, acc[2][3]);
            acc[2][4] = fmaf(p2, v1.x, acc[2][4]); acc[2][5] = fmaf(p2, v1.y, acc[2][5]);
            acc[2][6] = fmaf(p2, v1.z, acc[2][6]); acc[2][7] = fmaf(p2, v1.w, acc[2][7]);
            acc[3][0] = fmaf(p3, v0.x, acc[3][0]); acc[3][1] = fmaf(p3, v0.y, acc[3][1]);
            acc[3][2] = fmaf(p3, v0.z, acc[3][2]); acc[3][3] = fmaf(p3, v0.w, acc[3][3]);
            acc[3][4] = fmaf(p3, v1.x, acc[3][4]); acc[3][5] = fmaf(p3, v1.y, acc[3][5]);
            acc[3][6] = fmaf(p3, v1.z, acc[3][6]); acc[3][7] = fmaf(p3, v1.w, acc[3][7]);
        }
        __syncthreads();
    }

    // epilogue: normalize and write O in [L, H*HD] layout for final GEMM
    #pragma unroll
    for (int i = 0; i < 4; i++) {
        float rl = 1.0f / lsum[i];
        size_t base = (size_t)(qbase + r0 + i) * DMODEL + h * HDIM + c0o;
        float4 o0 = make_float4(acc[i][0] * rl, acc[i][1] * rl, acc[i][2] * rl, acc[i][3] * rl);
        float4 o1 = make_float4(acc[i][4] * rl, acc[i][5] * rl, acc[i][6] * rl, acc[i][7] * rl);
        *(float4*)&g_o[base]     = o0;
        *(float4*)&g_o[base + 4] = o1;
    }
}

// ---------------------------------------------------------------------------
// Launch
// ---------------------------------------------------------------------------
extern "C" void kernel_launch(void* const* d_in, const int* in_sizes, int n_in,
                              void* d_out, int out_size)
{
    const float* x     = (const float*)d_in[0];
    // d_in[1] = attention_mask (causal; applied analytically, unused)
    const float* cosp  = (const float*)d_in[2];
    const float* sinp  = (const float*)d_in[3];
    const float* w_qkv = (const float*)d_in[4];
    const float* w_o   = (const float*)d_in[5];
    float* out = (float*)d_out;

    float *qkv_p, *o_p;
    cudaGetSymbolAddress((void**)&qkv_p, g_qkv);
    cudaGetSymbolAddress((void**)&o_p, g_o);

    // 1. QKV projection: [2048,4096] @ [4096,6144]
    sgemm128<<<dim3(QKVN / 128, LSEQ / 128), 256>>>(x, w_qkv, qkv_p, LSEQ, QKVN, DMODEL);

    // 2. RoPE in-place on q and k slices
    rope_kernel<<<dim3(LSEQ, NH + NKV), 64>>>(cosp, sinp);

    // 3. Flash attention
    cudaFuncSetAttribute(attn_kernel, cudaFuncAttributeMaxDynamicSharedMemorySize, ATT_SMEM_BYTES);
    attn_kernel<<<dim3(LSEQ / 64, NH), 256, ATT_SMEM_BYTES>>>();

    // 4. Output projection: [2048,4096] @ [4096,4096]
    sgemm128<<<dim3(DMODEL / 128, LSEQ / 128), 256>>>(o_p, w_o, out, LSEQ, DMODEL, DMODEL);
}

// round 3
// speedup vs baseline: 1.6699x; 1.6699x over previous
#include <cuda_runtime.h>
#include <math.h>
#include <stdint.h>

// Problem constants
#define LSEQ 2048
#define DMODEL 4096
#define NH 32
#define NKV 8
#define HDIM 128
#define QKVN 6144            // 32*128 + 2*8*128
#define KOFF 4096
#define VOFF 5120
#define ATT_SCALE 0.08838834764831843f

// Scratch (no cudaMalloc allowed)
__device__ float g_qkv[(size_t)LSEQ * QKVN];       // 50 MB
__device__ float g_o[(size_t)LSEQ * DMODEL];       // 33 MB (attn out, tf32-rounded)
__device__ float g_xr[(size_t)LSEQ * DMODEL];      // 33 MB (tf32-rounded x)
__device__ float g_wqkvT[(size_t)QKVN * DMODEL];   // 100 MB ([N,K] tf32-rounded)
__device__ float g_woT[(size_t)DMODEL * DMODEL];   // 67 MB  ([N,K] tf32-rounded)

// ---------------------------------------------------------------------------
// Helpers (sm_80+ portable: cp.async + mma.sync tf32 only)
// ---------------------------------------------------------------------------
__device__ __forceinline__ uint32_t smem_u32(const void* p) {
    uint32_t a;
    asm("{ .reg .u64 t; cvta.to.shared.u64 t, %1; cvt.u32.u64 %0, t; }" : "=r"(a) : "l"(p));
    return a;
}
__device__ __forceinline__ float f32_to_tf32(float v) {
    uint32_t o;
    asm("cvt.rna.tf32.f32 %0, %1;" : "=r"(o) : "f"(v));
    return __uint_as_float(o);
}
#define CP_ASYNC16(dst, src) \
    asm volatile("cp.async.cg.shared.global [%0], [%1], 16;" :: "r"(dst), "l"(src))
#define CP_COMMIT() asm volatile("cp.async.commit_group;")
#define CP_WAIT(n)  asm volatile("cp.async.wait_group %0;" :: "n"(n))

__device__ __forceinline__ void mma_tf32(float* d, const uint32_t* a, const uint32_t* b) {
    asm volatile(
        "mma.sync.aligned.m16n8k8.row.col.f32.tf32.tf32.f32 "
        "{%0,%1,%2,%3}, {%4,%5,%6,%7}, {%8,%9}, {%0,%1,%2,%3};"
        : "+f"(d[0]), "+f"(d[1]), "+f"(d[2]), "+f"(d[3])
        : "r"(a[0]), "r"(a[1]), "r"(a[2]), "r"(a[3]), "r"(b[0]), "r"(b[1]));
}

// ---------------------------------------------------------------------------
// mma.sync tf32 GEMM: C[M,N] = A[M,K] @ BT[N,K]^T  (both K-major, tf32-rounded)
// CTA 128x128, K-tile 16, 4-stage cp.async, 8 warps (warp tile 32x64).
// ---------------------------------------------------------------------------
#define BM 128
#define BN 128
#define BK 16
#define NSTG 4
#define PADW 20                       // floats per smem row (16 + 4 pad)
#define ASTG (BM * PADW)              // 2560 floats
#define BSTG (BN * PADW)
#define STGF (ASTG + BSTG)            // 5120 floats = 20 KB
#define GEMM_SMEM (NSTG * STGF * 4)   // 80 KB

__global__ __launch_bounds__(256, 1) void gemm_mma(
    const float* __restrict__ A, const float* __restrict__ BT,
    float* __restrict__ C, int N, int K)
{
    extern __shared__ float sm[];
    const int tid = threadIdx.x;
    const int wid = tid >> 5, lane = tid & 31;
    const int wm = wid & 3, wn = wid >> 2;        // 4 x 2 warp grid
    const int g = lane >> 2, c = lane & 3;
    const int bm = blockIdx.y * BM, bn = blockIdx.x * BN;
    const int NC = K / BK;

    float acc[2][8][4];
    #pragma unroll
    for (int mf = 0; mf < 2; mf++)
        #pragma unroll
        for (int nf = 0; nf < 8; nf++)
            #pragma unroll
            for (int i = 0; i < 4; i++) acc[mf][nf][i] = 0.f;

    // loader: 4 cp.async(16B) per thread per stage
    auto load_stage = [&](int ct, int s) {
        float* base = sm + s * STGF;
        const int kt = ct * BK;
        #pragma unroll
        for (int h = 0; h < 2; h++) {
            int idx = tid + h * 256;
            int row = idx >> 2, c4 = idx & 3;
            CP_ASYNC16(smem_u32(base + row * PADW + c4 * 4),
                       A + (size_t)(bm + row) * K + kt + c4 * 4);
        }
        #pragma unroll
        for (int h = 0; h < 2; h++) {
            int idx = tid + h * 256;
            int row = idx >> 2, c4 = idx & 3;
            CP_ASYNC16(smem_u32(base + ASTG + row * PADW + c4 * 4),
                       BT + (size_t)(bn + row) * K + kt + c4 * 4);
        }
        CP_COMMIT();
    };

    #pragma unroll
    for (int s = 0; s < NSTG - 1; s++) load_stage(s, s);

    for (int ct = 0; ct < NC; ct++) {
        CP_WAIT(2);
        __syncthreads();

        // prefetch next stage (overwrites stage (ct-1)%NSTG — safe post-sync)
        if (ct + NSTG - 1 < NC) load_stage(ct + NSTG - 1, (ct + NSTG - 1) % NSTG);
        else CP_COMMIT();  // keep group count consistent

        const float* As = sm + (ct % NSTG) * STGF;
        const float* Bs = As + ASTG;

        #pragma unroll
        for (int kk = 0; kk < 2; kk++) {
            uint32_t af[2][4], bf[8][2];
            #pragma unroll
            for (int mf = 0; mf < 2; mf++) {
                const float* p = As + (wm * 32 + mf * 16 + g) * PADW + kk * 8 + c;
                af[mf][0] = __float_as_uint(p[0]);
                af[mf][1] = __float_as_uint(p[8 * PADW]);
                af[mf][2] = __float_as_uint(p[4]);
                af[mf][3] = __float_as_uint(p[8 * PADW + 4]);
            }
            #pragma unroll
            for (int nf = 0; nf < 8; nf++) {
                const float* p = Bs + (wn * 64 + nf * 8 + g) * PADW + kk * 8 + c;
                bf[nf][0] = __float_as_uint(p[0]);
                bf[nf][1] = __float_as_uint(p[4]);
            }
            #pragma unroll
            for (int mf = 0; mf < 2; mf++)
                #pragma unroll
                for (int nf = 0; nf < 8; nf++)
                    mma_tf32(acc[mf][nf], af[mf], bf[nf]);
        }
    }

    // epilogue
    #pragma unroll
    for (int mf = 0; mf < 2; mf++) {
        #pragma unroll
        for (int nf = 0; nf < 8; nf++) {
            int row = bm + wm * 32 + mf * 16 + g;
            int col = bn + wn * 64 + nf * 8 + 2 * c;
            *(float2*)&C[(size_t)row * N + col] = make_float2(acc[mf][nf][0], acc[mf][nf][1]);
            *(float2*)&C[(size_t)(row + 8) * N + col] = make_float2(acc[mf][nf][2], acc[mf][nf][3]);
        }
    }
}

// ---------------------------------------------------------------------------
// Transpose + tf32 round: dst[C][R] = rna(src[R][C])
// ---------------------------------------------------------------------------
__global__ void transpose_rna(const float* __restrict__ src, float* __restrict__ dst,
                              int R, int C)
{
    __shared__ float t[32][33];
    const int bx = blockIdx.x * 32, by = blockIdx.y * 32;
    const int x = threadIdx.x, y0 = threadIdx.y;
    #pragma unroll
    for (int i = 0; i < 4; i++) {
        int r = by + y0 + i * 8;
        t[y0 + i * 8][x] = f32_to_tf32(src[(size_t)r * C + bx + x]);
    }
    __syncthreads();
    #pragma unroll
    for (int i = 0; i < 4; i++) {
        int c = bx + y0 + i * 8;
        dst[(size_t)c * R + by + x] = t[x][y0 + i * 8];
    }
}

__global__ void rna_copy(const float* __restrict__ src, float* __restrict__ dst, int n4)
{
    int i = blockIdx.x * blockDim.x + threadIdx.x;
    if (i < n4) {
        float4 v = ((const float4*)src)[i];
        v.x = f32_to_tf32(v.x); v.y = f32_to_tf32(v.y);
        v.z = f32_to_tf32(v.z); v.w = f32_to_tf32(v.w);
        ((float4*)dst)[i] = v;
    }
}

// ---------------------------------------------------------------------------
// RoPE (in-place, with tf32 rounding since q/k feed the attn GEMM in fp32 now;
// keep full fp32 — attention is still CUDA-core fp32 this round)
// ---------------------------------------------------------------------------
__global__ void rope_kernel(const float* __restrict__ cosp,
                            const float* __restrict__ sinp)
{
    const int l = blockIdx.x;
    const int y = blockIdx.y;
    const int t = threadIdx.x;
    const int off = (y < NH) ? y * HDIM : KOFF + (y - NH) * HDIM;
    const size_t base = (size_t)l * QKVN + off;

    float v  = g_qkv[base + t];
    int pj   = (t < 32) ? t + 32 : t - 32;
    float pv = g_qkv[base + pj];
    float cc = cosp[l * 64 + t];
    float ss = sinp[l * 64 + t];
    float o = (t < 32) ? fmaf(v, cc, -pv * ss) : fmaf(v, cc, pv * ss);
    __syncthreads();
    g_qkv[base + t] = o;
}

// ---------------------------------------------------------------------------
// Flash attention (fp32 CUDA cores)
// ---------------------------------------------------------------------------
#define ATT_SMEM_FLOATS (64*128 + 128*68 + 64*128 + 64*64)
#define ATT_SMEM_BYTES  (ATT_SMEM_FLOATS * 4)

__global__ __launch_bounds__(256, 1) void attn_kernel()
{
    extern __shared__ float smf[];
    float* Qs  = smf;
    float* KsT = Qs  + 64 * 128;
    float* Vs  = KsT + 128 * 68;
    float* Ps  = Vs  + 64 * 128;

    const int qt = blockIdx.x;
    const int h  = blockIdx.y;
    const int kvh = h >> 2;
    const int qoff = h * HDIM;
    const int koff = KOFF + kvh * HDIM;
    const int voff = VOFF + kvh * HDIM;

    const int tid = threadIdx.x;
    const int tx = tid & 15, ty = tid >> 4;
    const int r0  = ty * 4;
    const int c0s = tx * 4;
    const int c0o = tx * 8;
    const int qbase = qt * 64;

    for (int i = tid; i < 64 * 32; i += 256) {
        int row = i >> 5, c4 = i & 31;
        float4 v = *(const float4*)&g_qkv[(size_t)(qbase + row) * QKVN + qoff + c4 * 4];
        *(float4*)&Qs[row * 128 + c4 * 4] = v;
    }

    float m[4], lsum[4], acc[4][8];
    #pragma unroll
    for (int i = 0; i < 4; i++) {
        m[i] = -1e30f; lsum[i] = 0.f;
        #pragma unroll
        for (int j = 0; j < 8; j++) acc[i][j] = 0.f;
    }
    __syncthreads();

    for (int kt = 0; kt <= qt; kt++) {
        const int kb = kt * 64;
        for (int i = tid; i < 64 * 32; i += 256) {
            int row = i >> 5, c4 = i & 31;
            float4 kv = *(const float4*)&g_qkv[(size_t)(kb + row) * QKVN + koff + c4 * 4];
            int d = c4 * 4;
            KsT[(d + 0) * 68 + row] = kv.x;
            KsT[(d + 1) * 68 + row] = kv.y;
            KsT[(d + 2) * 68 + row] = kv.z;
            KsT[(d + 3) * 68 + row] = kv.w;
            float4 vv = *(const float4*)&g_qkv[(size_t)(kb + row) * QKVN + voff + c4 * 4];
            *(float4*)&Vs[row * 128 + c4 * 4] = vv;
        }
        __syncthreads();

        float s[4][4];
        #pragma unroll
        for (int i = 0; i < 4; i++)
            #pragma unroll
            for (int j = 0; j < 4; j++) s[i][j] = 0.f;

        #pragma unroll 4
        for (int d = 0; d < 128; d++) {
            float q0 = Qs[(r0 + 0) * 128 + d];
            float q1 = Qs[(r0 + 1) * 128 + d];
            float q2 = Qs[(r0 + 2) * 128 + d];
            float q3 = Qs[(r0 + 3) * 128 + d];
            float4 kv = *(const float4*)&KsT[d * 68 + c0s];
            s[0][0] = fmaf(q0, kv.x, s[0][0]); s[0][1] = fmaf(q0, kv.y, s[0][1]);
            s[0][2] = fmaf(q0, kv.z, s[0][2]); s[0][3] = fmaf(q0, kv.w, s[0][3]);
            s[1][0] = fmaf(q1, kv.x, s[1][0]); s[1][1] = fmaf(q1, kv.y, s[1][1]);
            s[1][2] = fmaf(q1, kv.z, s[1][2]); s[1][3] = fmaf(q1, kv.w, s[1][3]);
            s[2][0] = fmaf(q2, kv.x, s[2][0]); s[2][1] = fmaf(q2, kv.y, s[2][1]);
            s[2][2] = fmaf(q2, kv.z, s[2][2]); s[2][3] = fmaf(q2, kv.w, s[2][3]);
            s[3][0] = fmaf(q3, kv.x, s[3][0]); s[3][1] = fmaf(q3, kv.y, s[3][1]);
            s[3][2] = fmaf(q3, kv.z, s[3][2]); s[3][3] = fmaf(q3, kv.w, s[3][3]);
        }

        #pragma unroll
        for (int i = 0; i < 4; i++) {
            int qr = qbase + r0 + i;
            #pragma unroll
            for (int j = 0; j < 4; j++) {
                s[i][j] *= ATT_SCALE;
                if (kb + c0s + j > qr) s[i][j] = -1e30f;
            }
        }

        #pragma unroll
        for (int i = 0; i < 4; i++) {
            float tmax = fmaxf(fmaxf(s[i][0], s[i][1]), fmaxf(s[i][2], s[i][3]));
            #pragma unroll
            for (int msk = 1; msk < 16; msk <<= 1)
                tmax = fmaxf(tmax, __shfl_xor_sync(0xffffffffu, tmax, msk, 32));
            float mn = fmaxf(m[i], tmax);
            float corr = __expf(m[i] - mn);
            m[i] = mn;

            float p0 = __expf(s[i][0] - mn);
            float p1 = __expf(s[i][1] - mn);
            float p2 = __expf(s[i][2] - mn);
            float p3 = __expf(s[i][3] - mn);
            *(float4*)&Ps[(r0 + i) * 64 + c0s] = make_float4(p0, p1, p2, p3);

            float rs = p0 + p1 + p2 + p3;
            #pragma unroll
            for (int msk = 1; msk < 16; msk <<= 1)
                rs += __shfl_xor_sync(0xffffffffu, rs, msk, 32);
            lsum[i] = lsum[i] * corr + rs;

            #pragma unroll
            for (int j = 0; j < 8; j++) acc[i][j] *= corr;
        }
        __syncwarp();

        #pragma unroll 4
        for (int k = 0; k < 64; k++) {
            float p0 = Ps[(r0 + 0) * 64 + k];
            float p1 = Ps[(r0 + 1) * 64 + k];
            float p2 = Ps[(r0 + 2) * 64 + k];
            float p3 = Ps[(r0 + 3) * 64 + k];
            float4 v0 = *(const float4*)&Vs[k * 128 + c0o];
            float4 v1 = *(const float4*)&Vs[k * 128 + c0o + 4];
            acc[0][0] = fmaf(p0, v0.x, acc[0][0]); acc[0][1] = fmaf(p0, v0.y, acc[0][1]);
            acc[0][2] = fmaf(p0, v0.z, acc[0][2]); acc[0][3] = fmaf(p0, v0.w, acc[0][3]);
            acc[0][4] = fmaf(p0, v1.x, acc[0][4]); acc[0][5] = fmaf(p0, v1.y, acc[0][5]);
            acc[0][6] = fmaf(p0, v1.z, acc[0][6]); acc[0][7] = fmaf(p0, v1.w, acc[0][7]);
            acc[1][0] = fmaf(p1, v0.x, acc[1][0]); acc[1][1] = fmaf(p1, v0.y, acc[1][1]);
            acc[1][2] = fmaf(p1, v0.z, acc[1][2]); acc[1][3] = fmaf(p1, v0.w, acc[1][3]);
            acc[1][4] = fmaf(p1, v1.x, acc[1][4]); acc[1][5] = fmaf(p1, v1.y, acc[1][5]);
            acc[1][6] = fmaf(p1, v1.z, acc[1][6]); acc[1][7] = fmaf(p1, v1.w, acc[1][7]);
            acc[2][0] = fmaf(p2, v0.x, acc[2][0]); acc[2][1] = fmaf(p2, v0.y, acc[2][1]);
            acc[2][2] = fmaf(p2, v0.z, acc[2][2]); acc[2][3] = fmaf(p2, v0.w, acc[2][3]);
            acc[2][4] = fmaf(p2, v1.x, acc[2][4]); acc[2][5] = fmaf(p2, v1.y, acc[2][5]);
            acc[2][6] = fmaf(p2, v1.z, acc[2][6]); acc[2][7] = fmaf(p2, v1.w, acc[2][7]);
            acc[3][0] = fmaf(p3, v0.x, acc[3][0]); acc[3][1] = fmaf(p3, v0.y, acc[3][1]);
            acc[3][2] = fmaf(p3, v0.z, acc[3][2]); acc[3][3] = fmaf(p3, v0.w, acc[3][3]);
            acc[3][4] = fmaf(p3, v1.x, acc[3][4]); acc[3][5] = fmaf(p3, v1.y, acc[3][5]);
            acc[3][6] = fmaf(p3, v1.z, acc[3][6]); acc[3][7] = fmaf(p3, v1.w, acc[3][7]);
        }
        __syncthreads();
    }

    #pragma unroll
    for (int i = 0; i < 4; i++) {
        float rl = 1.0f / lsum[i];
        size_t base = (size_t)(qbase + r0 + i) * DMODEL + h * HDIM + c0o;
        float4 o0 = make_float4(f32_to_tf32(acc[i][0] * rl), f32_to_tf32(acc[i][1] * rl),
                                f32_to_tf32(acc[i][2] * rl), f32_to_tf32(acc[i][3] * rl));
        float4 o1 = make_float4(f32_to_tf32(acc[i][4] * rl), f32_to_tf32(acc[i][5] * rl),
                                f32_to_tf32(acc[i][6] * rl), f32_to_tf32(acc[i][7] * rl));
        *(float4*)&g_o[base]     = o0;
        *(float4*)&g_o[base + 4] = o1;
    }
}

// ---------------------------------------------------------------------------
// Launch
// ---------------------------------------------------------------------------
extern "C" void kernel_launch(void* const* d_in, const int* in_sizes, int n_in,
                              void* d_out, int out_size)
{
    const float* x     = (const float*)d_in[0];
    const float* cosp  = (const float*)d_in[2];
    const float* sinp  = (const float*)d_in[3];
    const float* w_qkv = (const float*)d_in[4];
    const float* w_o   = (const float*)d_in[5];
    float* out = (float*)d_out;

    float *qkv_p, *o_p, *xr_p, *wqkvT_p, *woT_p;
    cudaGetSymbolAddress((void**)&qkv_p, g_qkv);
    cudaGetSymbolAddress((void**)&o_p, g_o);
    cudaGetSymbolAddress((void**)&xr_p, g_xr);
    cudaGetSymbolAddress((void**)&wqkvT_p, g_wqkvT);
    cudaGetSymbolAddress((void**)&woT_p, g_woT);

    cudaFuncSetAttribute(gemm_mma, cudaFuncAttributeMaxDynamicSharedMemorySize, GEMM_SMEM);
    cudaFuncSetAttribute(attn_kernel, cudaFuncAttributeMaxDynamicSharedMemorySize, ATT_SMEM_BYTES);

    // 0. tf32-round inputs / transpose weights to K-major
    rna_copy<<<(LSEQ * DMODEL / 4 + 255) / 256, 256>>>(x, xr_p, LSEQ * DMODEL / 4);
    transpose_rna<<<dim3(QKVN / 32, DMODEL / 32), dim3(32, 8)>>>(w_qkv, wqkvT_p, DMODEL, QKVN);
    transpose_rna<<<dim3(DMODEL / 32, DMODEL / 32), dim3(32, 8)>>>(w_o, woT_p, DMODEL, DMODEL);

    // 1. QKV projection (tensor cores, tf32 mma.sync)
    gemm_mma<<<dim3(QKVN / BN, LSEQ / BM), 256, GEMM_SMEM>>>(xr_p, wqkvT_p, qkv_p, QKVN, DMODEL);

    // 2. RoPE
    rope_kernel<<<dim3(LSEQ, NH + NKV), 64>>>(cosp, sinp);

    // 3. Flash attention (fp32)
    attn_kernel<<<dim3(LSEQ / 64, NH), 256, ATT_SMEM_BYTES>>>();

    // 4. Output projection (tensor cores, tf32 mma.sync)
    gemm_mma<<<dim3(DMODEL / BN, LSEQ / BM), 256, GEMM_SMEM>>>(o_p, woT_p, out, DMODEL, DMODEL);
}

// round 4
// speedup vs baseline: 2.5766x; 1.5430x over previous
#include <cuda_runtime.h>
#include <cuda_bf16.h>
#include <math.h>
#include <stdint.h>

// Problem constants
#define LSEQ 2048
#define DMODEL 4096
#define NH 32
#define NKV 8
#define HDIM 128
#define QKVN 6144            // 32*128 + 2*8*128
#define KOFF 4096
#define VOFF 5120
#define ATT_SCALE 0.08838834764831843f
#define LOG2E 1.44269504089f

// Scratch (no cudaMalloc allowed)
__device__ float g_qkv[(size_t)LSEQ * QKVN];       // 50 MB
__device__ float g_o[(size_t)LSEQ * DMODEL];       // 33 MB (attn out, tf32-rounded)
__device__ float g_xr[(size_t)LSEQ * DMODEL];      // 33 MB (tf32-rounded x)
__device__ float g_wqkvT[(size_t)QKVN * DMODEL];   // 100 MB ([N,K] tf32-rounded)
__device__ float g_woT[(size_t)DMODEL * DMODEL];   // 67 MB  ([N,K] tf32-rounded)

// ---------------------------------------------------------------------------
// Helpers (sm_80+ portable)
// ---------------------------------------------------------------------------
__device__ __forceinline__ uint32_t smem_u32(const void* p) {
    uint32_t a;
    asm("{ .reg .u64 t; cvta.to.shared.u64 t, %1; cvt.u32.u64 %0, t; }" : "=r"(a) : "l"(p));
    return a;
}
__device__ __forceinline__ float f32_to_tf32(float v) {
    uint32_t o;
    asm("cvt.rna.tf32.f32 %0, %1;" : "=r"(o) : "f"(v));
    return __uint_as_float(o);
}
#define CP_ASYNC16(dst, src) \
    asm volatile("cp.async.cg.shared.global [%0], [%1], 16;" :: "r"(dst), "l"(src))
#define CP_COMMIT() asm volatile("cp.async.commit_group;")
#define CP_WAIT(n)  asm volatile("cp.async.wait_group %0;" :: "n"(n))

__device__ __forceinline__ void mma_tf32(float* d, const uint32_t* a, const uint32_t* b) {
    asm volatile(
        "mma.sync.aligned.m16n8k8.row.col.f32.tf32.tf32.f32 "
        "{%0,%1,%2,%3}, {%4,%5,%6,%7}, {%8,%9}, {%0,%1,%2,%3};"
        : "+f"(d[0]), "+f"(d[1]), "+f"(d[2]), "+f"(d[3])
        : "r"(a[0]), "r"(a[1]), "r"(a[2]), "r"(a[3]), "r"(b[0]), "r"(b[1]));
}
__device__ __forceinline__ void mma_bf16(float* d, const uint32_t* a, const uint32_t* b) {
    asm volatile(
        "mma.sync.aligned.m16n8k16.row.col.f32.bf16.bf16.f32 "
        "{%0,%1,%2,%3}, {%4,%5,%6,%7}, {%8,%9}, {%0,%1,%2,%3};"
        : "+f"(d[0]), "+f"(d[1]), "+f"(d[2]), "+f"(d[3])
        : "r"(a[0]), "r"(a[1]), "r"(a[2]), "r"(a[3]), "r"(b[0]), "r"(b[1]));
}

// Pack (v0, v1) into bf16x2 hi word and residual-lo word. v0 -> low half.
__device__ __forceinline__ void pack_hilo(float v0, float v1, uint32_t& hi, uint32_t& lo) {
    __nv_bfloat162 h2 = __floats2bfloat162_rn(v0, v1);
    uint32_t hw = *(uint32_t*)&h2;
    float h0 = __uint_as_float(hw << 16);
    float h1 = __uint_as_float(hw & 0xffff0000u);
    __nv_bfloat162 l2 = __floats2bfloat162_rn(v0 - h0, v1 - h1);
    hi = hw;
    lo = *(uint32_t*)&l2;
}

// ---------------------------------------------------------------------------
// mma.sync tf32 GEMM (unchanged from R3): C[M,N] = A[M,K] @ BT[N,K]^T
// ---------------------------------------------------------------------------
#define BM 128
#define BN 128
#define BK 16
#define NSTG 4
#define PADW 20
#define ASTG (BM * PADW)
#define BSTG (BN * PADW)
#define STGF (ASTG + BSTG)
#define GEMM_SMEM (NSTG * STGF * 4)

__global__ __launch_bounds__(256, 1) void gemm_mma(
    const float* __restrict__ A, const float* __restrict__ BT,
    float* __restrict__ C, int N, int K)
{
    extern __shared__ float sm[];
    const int tid = threadIdx.x;
    const int wid = tid >> 5, lane = tid & 31;
    const int wm = wid & 3, wn = wid >> 2;
    const int g = lane >> 2, c = lane & 3;
    const int bm = blockIdx.y * BM, bn = blockIdx.x * BN;
    const int NC = K / BK;

    float acc[2][8][4];
    #pragma unroll
    for (int mf = 0; mf < 2; mf++)
        #pragma unroll
        for (int nf = 0; nf < 8; nf++)
            #pragma unroll
            for (int i = 0; i < 4; i++) acc[mf][nf][i] = 0.f;

    auto load_stage = [&](int ct, int s) {
        float* base = sm + s * STGF;
        const int kt = ct * BK;
        #pragma unroll
        for (int h = 0; h < 2; h++) {
            int idx = tid + h * 256;
            int row = idx >> 2, c4 = idx & 3;
            CP_ASYNC16(smem_u32(base + row * PADW + c4 * 4),
                       A + (size_t)(bm + row) * K + kt + c4 * 4);
        }
        #pragma unroll
        for (int h = 0; h < 2; h++) {
            int idx = tid + h * 256;
            int row = idx >> 2, c4 = idx & 3;
            CP_ASYNC16(smem_u32(base + ASTG + row * PADW + c4 * 4),
                       BT + (size_t)(bn + row) * K + kt + c4 * 4);
        }
        CP_COMMIT();
    };

    #pragma unroll
    for (int s = 0; s < NSTG - 1; s++) load_stage(s, s);

    for (int ct = 0; ct < NC; ct++) {
        CP_WAIT(2);
        __syncthreads();
        if (ct + NSTG - 1 < NC) load_stage(ct + NSTG - 1, (ct + NSTG - 1) % NSTG);
        else CP_COMMIT();

        const float* As = sm + (ct % NSTG) * STGF;
        const float* Bs = As + ASTG;

        #pragma unroll
        for (int kk = 0; kk < 2; kk++) {
            uint32_t af[2][4], bf[8][2];
            #pragma unroll
            for (int mf = 0; mf < 2; mf++) {
                const float* p = As + (wm * 32 + mf * 16 + g) * PADW + kk * 8 + c;
                af[mf][0] = __float_as_uint(p[0]);
                af[mf][1] = __float_as_uint(p[8 * PADW]);
                af[mf][2] = __float_as_uint(p[4]);
                af[mf][3] = __float_as_uint(p[8 * PADW + 4]);
            }
            #pragma unroll
            for (int nf = 0; nf < 8; nf++) {
                const float* p = Bs + (wn * 64 + nf * 8 + g) * PADW + kk * 8 + c;
                bf[nf][0] = __float_as_uint(p[0]);
                bf[nf][1] = __float_as_uint(p[4]);
            }
            #pragma unroll
            for (int mf = 0; mf < 2; mf++)
                #pragma unroll
                for (int nf = 0; nf < 8; nf++)
                    mma_tf32(acc[mf][nf], af[mf], bf[nf]);
        }
    }

    #pragma unroll
    for (int mf = 0; mf < 2; mf++) {
        #pragma unroll
        for (int nf = 0; nf < 8; nf++) {
            int row = bm + wm * 32 + mf * 16 + g;
            int col = bn + wn * 64 + nf * 8 + 2 * c;
            *(float2*)&C[(size_t)row * N + col] = make_float2(acc[mf][nf][0], acc[mf][nf][1]);
            *(float2*)&C[(size_t)(row + 8) * N + col] = make_float2(acc[mf][nf][2], acc[mf][nf][3]);
        }
    }
}

// ---------------------------------------------------------------------------
// Transpose + tf32 round / elementwise round (unchanged)
// ---------------------------------------------------------------------------
__global__ void transpose_rna(const float* __restrict__ src, float* __restrict__ dst,
                              int R, int C)
{
    __shared__ float t[32][33];
    const int bx = blockIdx.x * 32, by = blockIdx.y * 32;
    const int x = threadIdx.x, y0 = threadIdx.y;
    #pragma unroll
    for (int i = 0; i < 4; i++) {
        int r = by + y0 + i * 8;
        t[y0 + i * 8][x] = f32_to_tf32(src[(size_t)r * C + bx + x]);
    }
    __syncthreads();
    #pragma unroll
    for (int i = 0; i < 4; i++) {
        int c = bx + y0 + i * 8;
        dst[(size_t)c * R + by + x] = t[x][y0 + i * 8];
    }
}

__global__ void rna_copy(const float* __restrict__ src, float* __restrict__ dst, int n4)
{
    int i = blockIdx.x * blockDim.x + threadIdx.x;
    if (i < n4) {
        float4 v = ((const float4*)src)[i];
        v.x = f32_to_tf32(v.x); v.y = f32_to_tf32(v.y);
        v.z = f32_to_tf32(v.z); v.w = f32_to_tf32(v.w);
        ((float4*)dst)[i] = v;
    }
}

// ---------------------------------------------------------------------------
// RoPE (unchanged)
// ---------------------------------------------------------------------------
__global__ void rope_kernel(const float* __restrict__ cosp,
                            const float* __restrict__ sinp)
{
    const int l = blockIdx.x;
    const int y = blockIdx.y;
    const int t = threadIdx.x;
    const int off = (y < NH) ? y * HDIM : KOFF + (y - NH) * HDIM;
    const size_t base = (size_t)l * QKVN + off;

    float v  = g_qkv[base + t];
    int pj   = (t < 32) ? t + 32 : t - 32;
    float pv = g_qkv[base + pj];
    float cc = cosp[l * 64 + t];
    float ss = sinp[l * 64 + t];
    float o = (t < 32) ? fmaf(v, cc, -pv * ss) : fmaf(v, cc, pv * ss);
    __syncthreads();
    g_qkv[base + t] = o;
}

// ---------------------------------------------------------------------------
// Flash attention: bf16 hi/lo split mma (3-term, ~fp32 accuracy).
// CTA = (qtile of 128 rows) x (head). 256 threads, 8 warps x 16 q-rows.
// K-tile = 64 keys. S fragments reused directly as P A-fragments.
// ---------------------------------------------------------------------------
#define QW 68                 // words per Q/K smem row (64 data + 4 pad)
#define VW 37                 // words per Vt smem row (32 data + 5 pad)
#define QHI_OFF 0
#define QLO_OFF (128 * QW)                    // 8704
#define KHI_OFF (QLO_OFF + 128 * QW)          // 17408
#define KLO_OFF (KHI_OFF + 64 * QW)           // 21760
#define VTH_OFF (KLO_OFF + 64 * QW)           // 26112
#define VTL_OFF (VTH_OFF + 128 * VW)          // 30848
#define ATT_SMEM_WORDS (VTL_OFF + 128 * VW)   // 35584
#define ATT_SMEM_BYTES (ATT_SMEM_WORDS * 4)   // 142336

__global__ __launch_bounds__(256, 1) void attn_kernel()
{
    extern __shared__ uint32_t sw[];

    const int qt = (int)gridDim.x - 1 - (int)blockIdx.x;   // heavy tiles first
    const int h  = blockIdx.y;
    const int kvh = h >> 2;
    const int qoff = h * HDIM;
    const int koff = KOFF + kvh * HDIM;
    const int voff = VOFF + kvh * HDIM;
    const int qbase = qt * 128;

    const int tid = threadIdx.x;
    const int w = tid >> 5, lane = tid & 31;
    const int g = lane >> 2, cc = lane & 3;

    // ---- load Q tile (128 x 128) as bf16 hi/lo ----
    #pragma unroll
    for (int i = 0; i < 16; i++) {
        int idx = tid + i * 256;
        int row = idx >> 5, c4 = idx & 31;
        float4 v = *(const float4*)&g_qkv[(size_t)(qbase + row) * QKVN + qoff + c4 * 4];
        uint32_t h0, l0, h1, l1;
        pack_hilo(v.x, v.y, h0, l0);
        pack_hilo(v.z, v.w, h1, l1);
        int wo = row * QW + c4 * 2;
        sw[QHI_OFF + wo] = h0; sw[QHI_OFF + wo + 1] = h1;
        sw[QLO_OFF + wo] = l0; sw[QLO_OFF + wo + 1] = l1;
    }

    // softmax state (rows g and g+8 of this warp's 16)
    float m0 = -1e30f, m1 = -1e30f, l0s = 0.f, l1s = 0.f;
    float o[16][4];
    #pragma unroll
    for (int j = 0; j < 16; j++)
        #pragma unroll
        for (int i = 0; i < 4; i++) o[j][i] = 0.f;

    const int r0 = qbase + w * 16 + g;
    const int r1 = r0 + 8;
    const float sl2e = ATT_SCALE * LOG2E;
    const int nkt = 2 * qt + 2;

    for (int kt = 0; kt < nkt; kt++) {
        const int kb = kt * 64;
        __syncthreads();   // protect K/V smem from previous iteration's readers

        // ---- load K tile (64 x 128) hi/lo ----
        #pragma unroll
        for (int i = 0; i < 8; i++) {
            int idx = tid + i * 256;
            int row = idx >> 5, c4 = idx & 31;
            float4 v = *(const float4*)&g_qkv[(size_t)(kb + row) * QKVN + koff + c4 * 4];
            uint32_t h0, l0, h1, l1;
            pack_hilo(v.x, v.y, h0, l0);
            pack_hilo(v.z, v.w, h1, l1);
            int wo = row * QW + c4 * 2;
            sw[KHI_OFF + wo] = h0; sw[KHI_OFF + wo + 1] = h1;
            sw[KLO_OFF + wo] = l0; sw[KLO_OFF + wo + 1] = l1;
        }
        // ---- load V tile transposed: Vt[d][key], packed pairs along key ----
        {
            const int d = (w & 3) * 32 + lane;
            const int kp0 = (w >> 2) * 16;
            #pragma unroll
            for (int i = 0; i < 16; i++) {
                int kp = kp0 + i;
                float v0 = g_qkv[(size_t)(kb + 2 * kp) * QKVN + voff + d];
                float v1 = g_qkv[(size_t)(kb + 2 * kp + 1) * QKVN + voff + d];
                uint32_t hv, lv;
                pack_hilo(v0, v1, hv, lv);
                sw[VTH_OFF + d * VW + kp] = hv;
                sw[VTL_OFF + d * VW + kp] = lv;
            }
        }
        __syncthreads();

        // ---- S = Q @ K^T (bf16 3-term split) ----
        float s[8][4];
        #pragma unroll
        for (int j = 0; j < 8; j++)
            #pragma unroll
            for (int i = 0; i < 4; i++) s[j][i] = 0.f;

        #pragma unroll
        for (int kk = 0; kk < 8; kk++) {
            uint32_t ah[4], al[4];
            int ab = (w * 16 + g) * QW + kk * 8 + cc;
            ah[0] = sw[QHI_OFF + ab];            al[0] = sw[QLO_OFF + ab];
            ah[1] = sw[QHI_OFF + ab + 8 * QW];   al[1] = sw[QLO_OFF + ab + 8 * QW];
            ah[2] = sw[QHI_OFF + ab + 4];        al[2] = sw[QLO_OFF + ab + 4];
            ah[3] = sw[QHI_OFF + ab + 8 * QW + 4]; al[3] = sw[QLO_OFF + ab + 8 * QW + 4];
            #pragma unroll
            for (int j = 0; j < 8; j++) {
                uint32_t bh[2], bl[2];
                int bb = (j * 8 + g) * QW + kk * 8 + cc;
                bh[0] = sw[KHI_OFF + bb]; bh[1] = sw[KHI_OFF + bb + 4];
                bl[0] = sw[KLO_OFF + bb]; bl[1] = sw[KLO_OFF + bb + 4];
                mma_bf16(s[j], ah, bh);
                mma_bf16(s[j], al, bh);
                mma_bf16(s[j], ah, bl);
            }
        }

        // ---- causal mask (only the two diagonal ktiles need it) ----
        if (kt >= 2 * qt) {
            #pragma unroll
            for (int j = 0; j < 8; j++) {
                int colb = kb + j * 8 + 2 * cc;
                if (colb > r0)     s[j][0] = -1e30f;
                if (colb + 1 > r0) s[j][1] = -1e30f;
                if (colb > r1)     s[j][2] = -1e30f;
                if (colb + 1 > r1) s[j][3] = -1e30f;
            }
        }

        // ---- online softmax ----
        float mx0 = -1e30f, mx1 = -1e30f;
        #pragma unroll
        for (int j = 0; j < 8; j++) {
            mx0 = fmaxf(mx0, fmaxf(s[j][0], s[j][1]));
            mx1 = fmaxf(mx1, fmaxf(s[j][2], s[j][3]));
        }
        mx0 = fmaxf(mx0, __shfl_xor_sync(0xffffffffu, mx0, 1));
        mx0 = fmaxf(mx0, __shfl_xor_sync(0xffffffffu, mx0, 2));
        mx1 = fmaxf(mx1, __shfl_xor_sync(0xffffffffu, mx1, 1));
        mx1 = fmaxf(mx1, __shfl_xor_sync(0xffffffffu, mx1, 2));

        float mn0 = fmaxf(m0, mx0), mn1 = fmaxf(m1, mx1);
        float corr0 = exp2f((m0 - mn0) * sl2e);
        float corr1 = exp2f((m1 - mn1) * sl2e);
        m0 = mn0; m1 = mn1;

        uint32_t Ph0[8], Pl0[8], Ph1[8], Pl1[8];
        float sum0 = 0.f, sum1 = 0.f;
        #pragma unroll
        for (int j = 0; j < 8; j++) {
            float p0 = exp2f((s[j][0] - m0) * sl2e);
            float p1 = exp2f((s[j][1] - m0) * sl2e);
            float p2 = exp2f((s[j][2] - m1) * sl2e);
            float p3 = exp2f((s[j][3] - m1) * sl2e);
            sum0 += p0 + p1; sum1 += p2 + p3;
            pack_hilo(p0, p1, Ph0[j], Pl0[j]);
            pack_hilo(p2, p3, Ph1[j], Pl1[j]);
        }
        sum0 += __shfl_xor_sync(0xffffffffu, sum0, 1);
        sum0 += __shfl_xor_sync(0xffffffffu, sum0, 2);
        sum1 += __shfl_xor_sync(0xffffffffu, sum1, 1);
        sum1 += __shfl_xor_sync(0xffffffffu, sum1, 2);
        l0s = l0s * corr0 + sum0;
        l1s = l1s * corr1 + sum1;

        #pragma unroll
        for (int j = 0; j < 16; j++) {
            o[j][0] *= corr0; o[j][1] *= corr0;
            o[j][2] *= corr1; o[j][3] *= corr1;
        }

        // ---- O += P @ V (bf16 3-term split; P fragments from registers) ----
        #pragma unroll
        for (int kk = 0; kk < 4; kk++) {
            uint32_t ah[4] = {Ph0[2 * kk], Ph1[2 * kk], Ph0[2 * kk + 1], Ph1[2 * kk + 1]};
            uint32_t al[4] = {Pl0[2 * kk], Pl1[2 * kk], Pl0[2 * kk + 1], Pl1[2 * kk + 1]};
            #pragma unroll
            for (int jn = 0; jn < 16; jn++) {
                uint32_t bh[2], bl[2];
                int vb = (jn * 8 + g) * VW + kk * 8 + cc;
                bh[0] = sw[VTH_OFF + vb]; bh[1] = sw[VTH_OFF + vb + 4];
                bl[0] = sw[VTL_OFF + vb]; bl[1] = sw[VTL_OFF + vb + 4];
                mma_bf16(o[jn], ah, bh);
                mma_bf16(o[jn], al, bh);
                mma_bf16(o[jn], ah, bl);
            }
        }
    }

    // ---- epilogue: normalize, tf32-round, write [L, H*HD] ----
    float li0 = 1.0f / l0s, li1 = 1.0f / l1s;
    #pragma unroll
    for (int jn = 0; jn < 16; jn++) {
        int col = h * HDIM + jn * 8 + 2 * cc;
        *(float2*)&g_o[(size_t)r0 * DMODEL + col] =
            make_float2(f32_to_tf32(o[jn][0] * li0), f32_to_tf32(o[jn][1] * li0));
        *(float2*)&g_o[(size_t)r1 * DMODEL + col] =
            make_float2(f32_to_tf32(o[jn][2] * li1), f32_to_tf32(o[jn][3] * li1));
    }
}

// ---------------------------------------------------------------------------
// Launch
// ---------------------------------------------------------------------------
extern "C" void kernel_launch(void* const* d_in, const int* in_sizes, int n_in,
                              void* d_out, int out_size)
{
    const float* x     = (const float*)d_in[0];
    const float* cosp  = (const float*)d_in[2];
    const float* sinp  = (const float*)d_in[3];
    const float* w_qkv = (const float*)d_in[4];
    const float* w_o   = (const float*)d_in[5];
    float* out = (float*)d_out;

    float *qkv_p, *o_p, *xr_p, *wqkvT_p, *woT_p;
    cudaGetSymbolAddress((void**)&qkv_p, g_qkv);
    cudaGetSymbolAddress((void**)&o_p, g_o);
    cudaGetSymbolAddress((void**)&xr_p, g_xr);
    cudaGetSymbolAddress((void**)&wqkvT_p, g_wqkvT);
    cudaGetSymbolAddress((void**)&woT_p, g_woT);

    cudaFuncSetAttribute(gemm_mma, cudaFuncAttributeMaxDynamicSharedMemorySize, GEMM_SMEM);
    cudaFuncSetAttribute(attn_kernel, cudaFuncAttributeMaxDynamicSharedMemorySize, ATT_SMEM_BYTES);

    // 0. tf32-round inputs / transpose weights to K-major
    rna_copy<<<(LSEQ * DMODEL / 4 + 255) / 256, 256>>>(x, xr_p, LSEQ * DMODEL / 4);
    transpose_rna<<<dim3(QKVN / 32, DMODEL / 32), dim3(32, 8)>>>(w_qkv, wqkvT_p, DMODEL, QKVN);
    transpose_rna<<<dim3(DMODEL / 32, DMODEL / 32), dim3(32, 8)>>>(w_o, woT_p, DMODEL, DMODEL);

    // 1. QKV projection (tf32 mma)
    gemm_mma<<<dim3(QKVN / BN, LSEQ / BM), 256, GEMM_SMEM>>>(xr_p, wqkvT_p, qkv_p, QKVN, DMODEL);

    // 2. RoPE
    rope_kernel<<<dim3(LSEQ, NH + NKV), 64>>>(cosp, sinp);

    // 3. Flash attention (bf16 split mma tensor cores)
    attn_kernel<<<dim3(LSEQ / 128, NH), 256, ATT_SMEM_BYTES>>>();

    // 4. Output projection (tf32 mma)
    gemm_mma<<<dim3(DMODEL / BN, LSEQ / BM), 256, GEMM_SMEM>>>(o_p, woT_p, out, DMODEL, DMODEL);
}

// round 6
// speedup vs baseline: 2.9340x; 1.1387x over previous
#include <cuda_runtime.h>
#include <cuda_bf16.h>
#include <math.h>
#include <stdint.h>

// Problem constants
#define LSEQ 2048
#define DMODEL 4096
#define NH 32
#define NKV 8
#define HDIM 128
#define QKVN 6144            // 32*128 + 2*8*128
#define KOFF 4096
#define VOFF 5120
#define ATT_SCALE 0.08838834764831843f
#define LOG2E 1.44269504089f

// Scratch (no cudaMalloc allowed)
__device__ float g_qkv[(size_t)LSEQ * QKVN];       // 50 MB
__device__ float g_o[(size_t)LSEQ * DMODEL];       // 33 MB (attn out, tf32-rounded)
__device__ float g_xr[(size_t)LSEQ * DMODEL];      // 33 MB (tf32-rounded x)
__device__ float g_wqkvT[(size_t)QKVN * DMODEL];   // 100 MB ([N,K] tf32-rounded)
__device__ float g_woT[(size_t)DMODEL * DMODEL];   // 67 MB  ([N,K] tf32-rounded)

// ---------------------------------------------------------------------------
// Helpers (sm_80+ portable)
// ---------------------------------------------------------------------------
__device__ __forceinline__ uint32_t smem_u32(const void* p) {
    uint32_t a;
    asm("{ .reg .u64 t; cvta.to.shared.u64 t, %1; cvt.u32.u64 %0, t; }" : "=r"(a) : "l"(p));
    return a;
}
__device__ __forceinline__ float f32_to_tf32(float v) {
    uint32_t o;
    asm("cvt.rna.tf32.f32 %0, %1;" : "=r"(o) : "f"(v));
    return __uint_as_float(o);
}
#define CP_ASYNC16(dst, src) \
    asm volatile("cp.async.cg.shared.global [%0], [%1], 16;" :: "r"(dst), "l"(src))
#define CP_COMMIT() asm volatile("cp.async.commit_group;")
#define CP_WAIT(n)  asm volatile("cp.async.wait_group %0;" :: "n"(n))

__device__ __forceinline__ void mma_tf32(float* d, const uint32_t* a, const uint32_t* b) {
    asm volatile(
        "mma.sync.aligned.m16n8k8.row.col.f32.tf32.tf32.f32 "
        "{%0,%1,%2,%3}, {%4,%5,%6,%7}, {%8,%9}, {%0,%1,%2,%3};"
        : "+f"(d[0]), "+f"(d[1]), "+f"(d[2]), "+f"(d[3])
        : "r"(a[0]), "r"(a[1]), "r"(a[2]), "r"(a[3]), "r"(b[0]), "r"(b[1]));
}
__device__ __forceinline__ void mma_bf16(float* d, const uint32_t* a, const uint32_t* b) {
    asm volatile(
        "mma.sync.aligned.m16n8k16.row.col.f32.bf16.bf16.f32 "
        "{%0,%1,%2,%3}, {%4,%5,%6,%7}, {%8,%9}, {%0,%1,%2,%3};"
        : "+f"(d[0]), "+f"(d[1]), "+f"(d[2]), "+f"(d[3])
        : "r"(a[0]), "r"(a[1]), "r"(a[2]), "r"(a[3]), "r"(b[0]), "r"(b[1]));
}

// Pack (v0, v1) into bf16x2 hi word and residual-lo word. v0 -> low half.
__device__ __forceinline__ void pack_hilo(float v0, float v1, uint32_t& hi, uint32_t& lo) {
    __nv_bfloat162 h2 = __floats2bfloat162_rn(v0, v1);
    uint32_t hw = *(uint32_t*)&h2;
    float h0 = __uint_as_float(hw << 16);
    float h1 = __uint_as_float(hw & 0xffff0000u);
    __nv_bfloat162 l2 = __floats2bfloat162_rn(v0 - h0, v1 - h1);
    hi = hw;
    lo = *(uint32_t*)&l2;
}

// ---------------------------------------------------------------------------
// mma.sync tf32 GEMM: C[M,N] = A[M,K] @ BT[N,K]^T  (both K-major, tf32-rounded)
// CTA 128x128, K-tile 16, 4-stage cp.async, 8 warps (warp tile 32x64).
// launch_bounds(256,2): 2 CTAs/SM so barrier/LDS stalls of one CTA overlap
// the other's tensor issue (R4 ncu: occ 12.5%, issue 22.6%, tensor 34.7%).
// ---------------------------------------------------------------------------
#define BM 128
#define BN 128
#define BK 16
#define NSTG 4
#define PADW 20
#define ASTG (BM * PADW)
#define BSTG (BN * PADW)
#define STGF (ASTG + BSTG)
#define GEMM_SMEM (NSTG * STGF * 4)

__global__ __launch_bounds__(256, 2) void gemm_mma(
    const float* __restrict__ A, const float* __restrict__ BT,
    float* __restrict__ C, int N, int K)
{
    extern __shared__ float sm[];
    const int tid = threadIdx.x;
    const int wid = tid >> 5, lane = tid & 31;
    const int wm = wid & 3, wn = wid >> 2;
    const int g = lane >> 2, c = lane & 3;
    const int bm = blockIdx.y * BM, bn = blockIdx.x * BN;
    const int NC = K / BK;

    float acc[2][8][4];
    #pragma unroll
    for (int mf = 0; mf < 2; mf++)
        #pragma unroll
        for (int nf = 0; nf < 8; nf++)
            #pragma unroll
            for (int i = 0; i < 4; i++) acc[mf][nf][i] = 0.f;

    auto load_stage = [&](int ct, int s) {
        float* base = sm + s * STGF;
        const int kt = ct * BK;
        #pragma unroll
        for (int h = 0; h < 2; h++) {
            int idx = tid + h * 256;
            int row = idx >> 2, c4 = idx & 3;
            CP_ASYNC16(smem_u32(base + row * PADW + c4 * 4),
                       A + (size_t)(bm + row) * K + kt + c4 * 4);
        }
        #pragma unroll
        for (int h = 0; h < 2; h++) {
            int idx = tid + h * 256;
            int row = idx >> 2, c4 = idx & 3;
            CP_ASYNC16(smem_u32(base + ASTG + row * PADW + c4 * 4),
                       BT + (size_t)(bn + row) * K + kt + c4 * 4);
        }
        CP_COMMIT();
    };

    #pragma unroll
    for (int s = 0; s < NSTG - 1; s++) load_stage(s, s);

    for (int ct = 0; ct < NC; ct++) {
        CP_WAIT(2);
        __syncthreads();
        if (ct + NSTG - 1 < NC) load_stage(ct + NSTG - 1, (ct + NSTG - 1) % NSTG);
        else CP_COMMIT();

        const float* As = sm + (ct % NSTG) * STGF;
        const float* Bs = As + ASTG;

        #pragma unroll
        for (int kk = 0; kk < 2; kk++) {
            uint32_t af[2][4], bf[8][2];
            #pragma unroll
            for (int mf = 0; mf < 2; mf++) {
                const float* p = As + (wm * 32 + mf * 16 + g) * PADW + kk * 8 + c;
                af[mf][0] = __float_as_uint(p[0]);
                af[mf][1] = __float_as_uint(p[8 * PADW]);
                af[mf][2] = __float_as_uint(p[4]);
                af[mf][3] = __float_as_uint(p[8 * PADW + 4]);
            }
            #pragma unroll
            for (int nf = 0; nf < 8; nf++) {
                const float* p = Bs + (wn * 64 + nf * 8 + g) * PADW + kk * 8 + c;
                bf[nf][0] = __float_as_uint(p[0]);
                bf[nf][1] = __float_as_uint(p[4]);
            }
            #pragma unroll
            for (int mf = 0; mf < 2; mf++)
                #pragma unroll
                for (int nf = 0; nf < 8; nf++)
                    mma_tf32(acc[mf][nf], af[mf], bf[nf]);
        }
    }

    #pragma unroll
    for (int mf = 0; mf < 2; mf++) {
        #pragma unroll
        for (int nf = 0; nf < 8; nf++) {
            int row = bm + wm * 32 + mf * 16 + g;
            int col = bn + wn * 64 + nf * 8 + 2 * c;
            *(float2*)&C[(size_t)row * N + col] = make_float2(acc[mf][nf][0], acc[mf][nf][1]);
            *(float2*)&C[(size_t)(row + 8) * N + col] = make_float2(acc[mf][nf][2], acc[mf][nf][3]);
        }
    }
}

// ---------------------------------------------------------------------------
// Transpose + tf32 round / elementwise round
// ---------------------------------------------------------------------------
__global__ void transpose_rna(const float* __restrict__ src, float* __restrict__ dst,
                              int R, int C)
{
    __shared__ float t[32][33];
    const int bx = blockIdx.x * 32, by = blockIdx.y * 32;
    const int x = threadIdx.x, y0 = threadIdx.y;
    #pragma unroll
    for (int i = 0; i < 4; i++) {
        int r = by + y0 + i * 8;
        t[y0 + i * 8][x] = f32_to_tf32(src[(size_t)r * C + bx + x]);
    }
    __syncthreads();
    #pragma unroll
    for (int i = 0; i < 4; i++) {
        int c = bx + y0 + i * 8;
        dst[(size_t)c * R + by + x] = t[x][y0 + i * 8];
    }
}

__global__ void rna_copy(const float* __restrict__ src, float* __restrict__ dst, int n4)
{
    int i = blockIdx.x * blockDim.x + threadIdx.x;
    if (i < n4) {
        float4 v = ((const float4*)src)[i];
        v.x = f32_to_tf32(v.x); v.y = f32_to_tf32(v.y);
        v.z = f32_to_tf32(v.z); v.w = f32_to_tf32(v.w);
        ((float4*)dst)[i] = v;
    }
}

// ---------------------------------------------------------------------------
// RoPE
// ---------------------------------------------------------------------------
__global__ void rope_kernel(const float* __restrict__ cosp,
                            const float* __restrict__ sinp)
{
    const int l = blockIdx.x;
    const int y = blockIdx.y;
    const int t = threadIdx.x;
    const int off = (y < NH) ? y * HDIM : KOFF + (y - NH) * HDIM;
    const size_t base = (size_t)l * QKVN + off;

    float v  = g_qkv[base + t];
    int pj   = (t < 32) ? t + 32 : t - 32;
    float pv = g_qkv[base + pj];
    float cc = cosp[l * 64 + t];
    float ss = sinp[l * 64 + t];
    float o = (t < 32) ? fmaf(v, cc, -pv * ss) : fmaf(v, cc, pv * ss);
    __syncthreads();
    g_qkv[base + t] = o;
}

// ---------------------------------------------------------------------------
// Flash attention: bf16 hi/lo split mma (3-term, ~fp32 accuracy).
// ---------------------------------------------------------------------------
#define QW 68
#define VW 37
#define QHI_OFF 0
#define QLO_OFF (128 * QW)
#define KHI_OFF (QLO_OFF + 128 * QW)
#define KLO_OFF (KHI_OFF + 64 * QW)
#define VTH_OFF (KLO_OFF + 64 * QW)
#define VTL_OFF (VTH_OFF + 128 * VW)
#define ATT_SMEM_WORDS (VTL_OFF + 128 * VW)
#define ATT_SMEM_BYTES (ATT_SMEM_WORDS * 4)

__global__ __launch_bounds__(256, 1) void attn_kernel()
{
    extern __shared__ uint32_t sw[];

    const int qt = (int)gridDim.x - 1 - (int)blockIdx.x;
    const int h  = blockIdx.y;
    const int kvh = h >> 2;
    const int qoff = h * HDIM;
    const int koff = KOFF + kvh * HDIM;
    const int voff = VOFF + kvh * HDIM;
    const int qbase = qt * 128;

    const int tid = threadIdx.x;
    const int w = tid >> 5, lane = tid & 31;
    const int g = lane >> 2, cc = lane & 3;

    #pragma unroll
    for (int i = 0; i < 16; i++) {
        int idx = tid + i * 256;
        int row = idx >> 5, c4 = idx & 31;
        float4 v = *(const float4*)&g_qkv[(size_t)(qbase + row) * QKVN + qoff + c4 * 4];
        uint32_t h0, l0, h1, l1;
        pack_hilo(v.x, v.y, h0, l0);
        pack_hilo(v.z, v.w, h1, l1);
        int wo = row * QW + c4 * 2;
        sw[QHI_OFF + wo] = h0; sw[QHI_OFF + wo + 1] = h1;
        sw[QLO_OFF + wo] = l0; sw[QLO_OFF + wo + 1] = l1;
    }

    float m0 = -1e30f, m1 = -1e30f, l0s = 0.f, l1s = 0.f;
    float o[16][4];
    #pragma unroll
    for (int j = 0; j < 16; j++)
        #pragma unroll
        for (int i = 0; i < 4; i++) o[j][i] = 0.f;

    const int r0 = qbase + w * 16 + g;
    const int r1 = r0 + 8;
    const float sl2e = ATT_SCALE * LOG2E;
    const int nkt = 2 * qt + 2;

    for (int kt = 0; kt < nkt; kt++) {
        const int kb = kt * 64;
        __syncthreads();

        #pragma unroll
        for (int i = 0; i < 8; i++) {
            int idx = tid + i * 256;
            int row = idx >> 5, c4 = idx & 31;
            float4 v = *(const float4*)&g_qkv[(size_t)(kb + row) * QKVN + koff + c4 * 4];
            uint32_t h0, l0, h1, l1;
            pack_hilo(v.x, v.y, h0, l0);
            pack_hilo(v.z, v.w, h1, l1);
            int wo = row * QW + c4 * 2;
            sw[KHI_OFF + wo] = h0; sw[KHI_OFF + wo + 1] = h1;
            sw[KLO_OFF + wo] = l0; sw[KLO_OFF + wo + 1] = l1;
        }
        {
            const int d = (w & 3) * 32 + lane;
            const int kp0 = (w >> 2) * 16;
            #pragma unroll
            for (int i = 0; i < 16; i++) {
                int kp = kp0 + i;
                float v0 = g_qkv[(size_t)(kb + 2 * kp) * QKVN + voff + d];
                float v1 = g_qkv[(size_t)(kb + 2 * kp + 1) * QKVN + voff + d];
                uint32_t hv, lv;
                pack_hilo(v0, v1, hv, lv);
                sw[VTH_OFF + d * VW + kp] = hv;
                sw[VTL_OFF + d * VW + kp] = lv;
            }
        }
        __syncthreads();

        float s[8][4];
        #pragma unroll
        for (int j = 0; j < 8; j++)
            #pragma unroll
            for (int i = 0; i < 4; i++) s[j][i] = 0.f;

        #pragma unroll
        for (int kk = 0; kk < 8; kk++) {
            uint32_t ah[4], al[4];
            int ab = (w * 16 + g) * QW + kk * 8 + cc;
            ah[0] = sw[QHI_OFF + ab];            al[0] = sw[QLO_OFF + ab];
            ah[1] = sw[QHI_OFF + ab + 8 * QW];   al[1] = sw[QLO_OFF + ab + 8 * QW];
            ah[2] = sw[QHI_OFF + ab + 4];        al[2] = sw[QLO_OFF + ab + 4];
            ah[3] = sw[QHI_OFF + ab + 8 * QW + 4]; al[3] = sw[QLO_OFF + ab + 8 * QW + 4];
            #pragma unroll
            for (int j = 0; j < 8; j++) {
                uint32_t bh[2], bl[2];
                int bb = (j * 8 + g) * QW + kk * 8 + cc;
                bh[0] = sw[KHI_OFF + bb]; bh[1] = sw[KHI_OFF + bb + 4];
                bl[0] = sw[KLO_OFF + bb]; bl[1] = sw[KLO_OFF + bb + 4];
                mma_bf16(s[j], ah, bh);
                mma_bf16(s[j], al, bh);
                mma_bf16(s[j], ah, bl);
            }
        }

        if (kt >= 2 * qt) {
            #pragma unroll
            for (int j = 0; j < 8; j++) {
                int colb = kb + j * 8 + 2 * cc;
                if (colb > r0)     s[j][0] = -1e30f;
                if (colb + 1 > r0) s[j][1] = -1e30f;
                if (colb > r1)     s[j][2] = -1e30f;
                if (colb + 1 > r1) s[j][3] = -1e30f;
            }
        }

        float mx0 = -1e30f, mx1 = -1e30f;
        #pragma unroll
        for (int j = 0; j < 8; j++) {
            mx0 = fmaxf(mx0, fmaxf(s[j][0], s[j][1]));
            mx1 = fmaxf(mx1, fmaxf(s[j][2], s[j][3]));
        }
        mx0 = fmaxf(mx0, __shfl_xor_sync(0xffffffffu, mx0, 1));
        mx0 = fmaxf(mx0, __shfl_xor_sync(0xffffffffu, mx0, 2));
        mx1 = fmaxf(mx1, __shfl_xor_sync(0xffffffffu, mx1, 1));
        mx1 = fmaxf(mx1, __shfl_xor_sync(0xffffffffu, mx1, 2));

        float mn0 = fmaxf(m0, mx0), mn1 = fmaxf(m1, mx1);
        float corr0 = exp2f((m0 - mn0) * sl2e);
        float corr1 = exp2f((m1 - mn1) * sl2e);
        m0 = mn0; m1 = mn1;

        uint32_t Ph0[8], Pl0[8], Ph1[8], Pl1[8];
        float sum0 = 0.f, sum1 = 0.f;
        #pragma unroll
        for (int j = 0; j < 8; j++) {
            float p0 = exp2f((s[j][0] - m0) * sl2e);
            float p1 = exp2f((s[j][1] - m0) * sl2e);
            float p2 = exp2f((s[j][2] - m1) * sl2e);
            float p3 = exp2f((s[j][3] - m1) * sl2e);
            sum0 += p0 + p1; sum1 += p2 + p3;
            pack_hilo(p0, p1, Ph0[j], Pl0[j]);
            pack_hilo(p2, p3, Ph1[j], Pl1[j]);
        }
        sum0 += __shfl_xor_sync(0xffffffffu, sum0, 1);
        sum0 += __shfl_xor_sync(0xffffffffu, sum0, 2);
        sum1 += __shfl_xor_sync(0xffffffffu, sum1, 1);
        sum1 += __shfl_xor_sync(0xffffffffu, sum1, 2);
        l0s = l0s * corr0 + sum0;
        l1s = l1s * corr1 + sum1;

        #pragma unroll
        for (int j = 0; j < 16; j++) {
            o[j][0] *= corr0; o[j][1] *= corr0;
            o[j][2] *= corr1; o[j][3] *= corr1;
        }

        #pragma unroll
        for (int kk = 0; kk < 4; kk++) {
            uint32_t ah[4] = {Ph0[2 * kk], Ph1[2 * kk], Ph0[2 * kk + 1], Ph1[2 * kk + 1]};
            uint32_t al[4] = {Pl0[2 * kk], Pl1[2 * kk], Pl0[2 * kk + 1], Pl1[2 * kk + 1]};
            #pragma unroll
            for (int jn = 0; jn < 16; jn++) {
                uint32_t bh[2], bl[2];
                int vb = (jn * 8 + g) * VW + kk * 8 + cc;
                bh[0] = sw[VTH_OFF + vb]; bh[1] = sw[VTH_OFF + vb + 4];
                bl[0] = sw[VTL_OFF + vb]; bl[1] = sw[VTL_OFF + vb + 4];
                mma_bf16(o[jn], ah, bh);
                mma_bf16(o[jn], al, bh);
                mma_bf16(o[jn], ah, bl);
            }
        }
    }

    float li0 = 1.0f / l0s, li1 = 1.0f / l1s;
    #pragma unroll
    for (int jn = 0; jn < 16; jn++) {
        int col = h * HDIM + jn * 8 + 2 * cc;
        *(float2*)&g_o[(size_t)r0 * DMODEL + col] =
            make_float2(f32_to_tf32(o[jn][0] * li0), f32_to_tf32(o[jn][1] * li0));
        *(float2*)&g_o[(size_t)r1 * DMODEL + col] =
            make_float2(f32_to_tf32(o[jn][2] * li1), f32_to_tf32(o[jn][3] * li1));
    }
}

// ---------------------------------------------------------------------------
// Launch
// ---------------------------------------------------------------------------
extern "C" void kernel_launch(void* const* d_in, const int* in_sizes, int n_in,
                              void* d_out, int out_size)
{
    const float* x     = (const float*)d_in[0];
    const float* cosp  = (const float*)d_in[2];
    const float* sinp  = (const float*)d_in[3];
    const float* w_qkv = (const float*)d_in[4];
    const float* w_o   = (const float*)d_in[5];
    float* out = (float*)d_out;

    float *qkv_p, *o_p, *xr_p, *wqkvT_p, *woT_p;
    cudaGetSymbolAddress((void**)&qkv_p, g_qkv);
    cudaGetSymbolAddress((void**)&o_p, g_o);
    cudaGetSymbolAddress((void**)&xr_p, g_xr);
    cudaGetSymbolAddress((void**)&wqkvT_p, g_wqkvT);
    cudaGetSymbolAddress((void**)&woT_p, g_woT);

    cudaFuncSetAttribute(gemm_mma, cudaFuncAttributeMaxDynamicSharedMemorySize, GEMM_SMEM);
    cudaFuncSetAttribute(attn_kernel, cudaFuncAttributeMaxDynamicSharedMemorySize, ATT_SMEM_BYTES);

    // 0. tf32-round inputs / transpose weights to K-major
    rna_copy<<<(LSEQ * DMODEL / 4 + 255) / 256, 256>>>(x, xr_p, LSEQ * DMODEL / 4);
    transpose_rna<<<dim3(QKVN / 32, DMODEL / 32), dim3(32, 8)>>>(w_qkv, wqkvT_p, DMODEL, QKVN);
    transpose_rna<<<dim3(DMODEL / 32, DMODEL / 32), dim3(32, 8)>>>(w_o, woT_p, DMODEL, DMODEL);

    // 1. QKV projection (tf32 mma)
    gemm_mma<<<dim3(QKVN / BN, LSEQ / BM), 256, GEMM_SMEM>>>(xr_p, wqkvT_p, qkv_p, QKVN, DMODEL);

    // 2. RoPE
    rope_kernel<<<dim3(LSEQ, NH + NKV), 64>>>(cosp, sinp);

    // 3. Flash attention (bf16 split mma tensor cores)
    attn_kernel<<<dim3(LSEQ / 128, NH), 256, ATT_SMEM_BYTES>>>();

    // 4. Output projection (tf32 mma)
    gemm_mma<<<dim3(DMODEL / BN, LSEQ / BM), 256, GEMM_SMEM>>>(o_p, woT_p, out, DMODEL, DMODEL);
}

// round 7
// speedup vs baseline: 3.4385x; 1.1720x over previous
#include <cuda_runtime.h>
#include <cuda_bf16.h>
#include <math.h>
#include <stdint.h>

// Problem constants
#define LSEQ 2048
#define DMODEL 4096
#define NH 32
#define NKV 8
#define HDIM 128
#define QKVN 6144            // 32*128 + 2*8*128
#define KOFF 4096
#define VOFF 5120
#define ATT_SCALE 0.08838834764831843f
#define LOG2E 1.44269504089f

// Scratch (no cudaMalloc allowed)
__device__ float g_qkv[(size_t)LSEQ * QKVN];       // 50 MB
__device__ float g_o[(size_t)LSEQ * DMODEL];       // 33 MB
__device__ float g_xr[(size_t)LSEQ * DMODEL];      // 33 MB
__device__ float g_wqkvT[(size_t)QKVN * DMODEL];   // 100 MB
__device__ float g_woT[(size_t)DMODEL * DMODEL];   // 67 MB
// Packed bf16 hi/lo K and V^T (computed once post-RoPE, shared by all attn CTAs)
__device__ uint32_t g_kp[(size_t)NKV * LSEQ * 128];      // [kvh][l][hi 0..63 | lo 64..127]
__device__ uint32_t g_vtp[(size_t)NKV * HDIM * 2048];    // [kvh][d][hi kp 0..1023 | lo 1024..2047]

// ---------------------------------------------------------------------------
// Helpers
// ---------------------------------------------------------------------------
__device__ __forceinline__ uint32_t smem_u32(const void* p) {
    uint32_t a;
    asm("{ .reg .u64 t; cvta.to.shared.u64 t, %1; cvt.u32.u64 %0, t; }" : "=r"(a) : "l"(p));
    return a;
}
__device__ __forceinline__ float f32_to_tf32(float v) {
    uint32_t o;
    asm("cvt.rna.tf32.f32 %0, %1;" : "=r"(o) : "f"(v));
    return __uint_as_float(o);
}
#define CP_ASYNC16(dst, src) \
    asm volatile("cp.async.cg.shared.global [%0], [%1], 16;" :: "r"(dst), "l"(src))
#define CP_COMMIT() asm volatile("cp.async.commit_group;")
#define CP_WAIT(n)  asm volatile("cp.async.wait_group %0;" :: "n"(n))

__device__ __forceinline__ void mma_tf32(float* d, const uint32_t* a, const uint32_t* b) {
    asm volatile(
        "mma.sync.aligned.m16n8k8.row.col.f32.tf32.tf32.f32 "
        "{%0,%1,%2,%3}, {%4,%5,%6,%7}, {%8,%9}, {%0,%1,%2,%3};"
        : "+f"(d[0]), "+f"(d[1]), "+f"(d[2]), "+f"(d[3])
        : "r"(a[0]), "r"(a[1]), "r"(a[2]), "r"(a[3]), "r"(b[0]), "r"(b[1]));
}
__device__ __forceinline__ void mma_bf16(float* d, const uint32_t* a, const uint32_t* b) {
    asm volatile(
        "mma.sync.aligned.m16n8k16.row.col.f32.bf16.bf16.f32 "
        "{%0,%1,%2,%3}, {%4,%5,%6,%7}, {%8,%9}, {%0,%1,%2,%3};"
        : "+f"(d[0]), "+f"(d[1]), "+f"(d[2]), "+f"(d[3])
        : "r"(a[0]), "r"(a[1]), "r"(a[2]), "r"(a[3]), "r"(b[0]), "r"(b[1]));
}

// Pack (v0, v1) into bf16x2 hi word and residual-lo word. v0 -> low half.
__device__ __forceinline__ void pack_hilo(float v0, float v1, uint32_t& hi, uint32_t& lo) {
    __nv_bfloat162 h2 = __floats2bfloat162_rn(v0, v1);
    uint32_t hw = *(uint32_t*)&h2;
    float h0 = __uint_as_float(hw << 16);
    float h1 = __uint_as_float(hw & 0xffff0000u);
    __nv_bfloat162 l2 = __floats2bfloat162_rn(v0 - h0, v1 - h1);
    hi = hw;
    lo = *(uint32_t*)&l2;
}

// ---------------------------------------------------------------------------
// mma.sync tf32 GEMM: C[M,N] = A[M,K] @ BT[N,K]^T  (both K-major, tf32-rounded)
// CTA 128x128, K-tile 32 (halves barrier count vs BK=16), 3-stage cp.async,
// 8 warps (warp tile 32x64), 2 CTAs/SM.
// ---------------------------------------------------------------------------
#define BM 128
#define BN 128
#define BK 32
#define NSTG 3
#define PADW 36                        // 32 floats + 4 pad; 144B (16B-aligned rows)
#define ASTG (BM * PADW)
#define STGF (2 * BM * PADW)           // A + B per stage = 9216 floats
#define GEMM_SMEM (NSTG * STGF * 4)    // 110592 B

__global__ __launch_bounds__(256, 2) void gemm_mma(
    const float* __restrict__ A, const float* __restrict__ BT,
    float* __restrict__ C, int N, int K)
{
    extern __shared__ float sm[];
    const int tid = threadIdx.x;
    const int wid = tid >> 5, lane = tid & 31;
    const int wm = wid & 3, wn = wid >> 2;
    const int g = lane >> 2, c = lane & 3;
    const int bm = blockIdx.y * BM, bn = blockIdx.x * BN;
    const int NC = K / BK;

    float acc[2][8][4];
    #pragma unroll
    for (int mf = 0; mf < 2; mf++)
        #pragma unroll
        for (int nf = 0; nf < 8; nf++)
            #pragma unroll
            for (int i = 0; i < 4; i++) acc[mf][nf][i] = 0.f;

    auto load_stage = [&](int ct, int s) {
        float* base = sm + s * STGF;
        const int kt = ct * BK;
        #pragma unroll
        for (int h = 0; h < 4; h++) {
            int idx = tid + h * 256;            // 0..1023
            int row = idx >> 3, c8 = idx & 7;
            CP_ASYNC16(smem_u32(base + row * PADW + c8 * 4),
                       A + (size_t)(bm + row) * K + kt + c8 * 4);
        }
        #pragma unroll
        for (int h = 0; h < 4; h++) {
            int idx = tid + h * 256;
            int row = idx >> 3, c8 = idx & 7;
            CP_ASYNC16(smem_u32(base + ASTG + row * PADW + c8 * 4),
                       BT + (size_t)(bn + row) * K + kt + c8 * 4);
        }
        CP_COMMIT();
    };

    load_stage(0, 0);
    load_stage(1, 1);

    for (int ct = 0; ct < NC; ct++) {
        CP_WAIT(1);
        __syncthreads();
        if (ct + 2 < NC) load_stage(ct + 2, (ct + 2) % NSTG);
        else CP_COMMIT();

        const float* As = sm + (ct % NSTG) * STGF;
        const float* Bs = As + ASTG;

        #pragma unroll
        for (int kk = 0; kk < 4; kk++) {
            uint32_t af[2][4], bf[8][2];
            #pragma unroll
            for (int mf = 0; mf < 2; mf++) {
                const float* p = As + (wm * 32 + mf * 16 + g) * PADW + kk * 8 + c;
                af[mf][0] = __float_as_uint(p[0]);
                af[mf][1] = __float_as_uint(p[8 * PADW]);
                af[mf][2] = __float_as_uint(p[4]);
                af[mf][3] = __float_as_uint(p[8 * PADW + 4]);
            }
            #pragma unroll
            for (int nf = 0; nf < 8; nf++) {
                const float* p = Bs + (wn * 64 + nf * 8 + g) * PADW + kk * 8 + c;
                bf[nf][0] = __float_as_uint(p[0]);
                bf[nf][1] = __float_as_uint(p[4]);
            }
            #pragma unroll
            for (int mf = 0; mf < 2; mf++)
                #pragma unroll
                for (int nf = 0; nf < 8; nf++)
                    mma_tf32(acc[mf][nf], af[mf], bf[nf]);
        }
    }

    #pragma unroll
    for (int mf = 0; mf < 2; mf++) {
        #pragma unroll
        for (int nf = 0; nf < 8; nf++) {
            int row = bm + wm * 32 + mf * 16 + g;
            int col = bn + wn * 64 + nf * 8 + 2 * c;
            *(float2*)&C[(size_t)row * N + col] = make_float2(acc[mf][nf][0], acc[mf][nf][1]);
            *(float2*)&C[(size_t)(row + 8) * N + col] = make_float2(acc[mf][nf][2], acc[mf][nf][3]);
        }
    }
}

// ---------------------------------------------------------------------------
// Transpose + tf32 round / elementwise round
// ---------------------------------------------------------------------------
__global__ void transpose_rna(const float* __restrict__ src, float* __restrict__ dst,
                              int R, int C)
{
    __shared__ float t[32][33];
    const int bx = blockIdx.x * 32, by = blockIdx.y * 32;
    const int x = threadIdx.x, y0 = threadIdx.y;
    #pragma unroll
    for (int i = 0; i < 4; i++) {
        int r = by + y0 + i * 8;
        t[y0 + i * 8][x] = f32_to_tf32(src[(size_t)r * C + bx + x]);
    }
    __syncthreads();
    #pragma unroll
    for (int i = 0; i < 4; i++) {
        int c = bx + y0 + i * 8;
        dst[(size_t)c * R + by + x] = t[x][y0 + i * 8];
    }
}

__global__ void rna_copy(const float* __restrict__ src, float* __restrict__ dst, int n4)
{
    int i = blockIdx.x * blockDim.x + threadIdx.x;
    if (i < n4) {
        float4 v = ((const float4*)src)[i];
        v.x = f32_to_tf32(v.x); v.y = f32_to_tf32(v.y);
        v.z = f32_to_tf32(v.z); v.w = f32_to_tf32(v.w);
        ((float4*)dst)[i] = v;
    }
}

// ---------------------------------------------------------------------------
// RoPE
// ---------------------------------------------------------------------------
__global__ void rope_kernel(const float* __restrict__ cosp,
                            const float* __restrict__ sinp)
{
    const int l = blockIdx.x;
    const int y = blockIdx.y;
    const int t = threadIdx.x;
    const int off = (y < NH) ? y * HDIM : KOFF + (y - NH) * HDIM;
    const size_t base = (size_t)l * QKVN + off;

    float v  = g_qkv[base + t];
    int pj   = (t < 32) ? t + 32 : t - 32;
    float pv = g_qkv[base + pj];
    float cc = cosp[l * 64 + t];
    float ss = sinp[l * 64 + t];
    float o = (t < 32) ? fmaf(v, cc, -pv * ss) : fmaf(v, cc, pv * ss);
    __syncthreads();
    g_qkv[base + t] = o;
}

// ---------------------------------------------------------------------------
// Pack K (post-RoPE) to bf16 hi/lo words: g_kp[kvh][l][hi j | lo 64+j],
// word j = elements (2j, 2j+1).
// grid (LSEQ, NKV), 64 threads.
// ---------------------------------------------------------------------------
__global__ void pack_k_kernel()
{
    const int l = blockIdx.x, kvh = blockIdx.y, j = threadIdx.x;
    const float* src = &g_qkv[(size_t)l * QKVN + KOFF + kvh * HDIM];
    uint32_t hi, lo;
    pack_hilo(src[2 * j], src[2 * j + 1], hi, lo);
    uint32_t* dst = &g_kp[((size_t)kvh * LSEQ + l) * 128];
    dst[j] = hi;
    dst[64 + j] = lo;
}

// ---------------------------------------------------------------------------
// Pack V transposed: g_vtp[kvh][d][hi kp | lo 1024+kp], word kp = (v[2kp], v[2kp+1]).
// grid (LSEQ/64, NKV), 256 threads; smem-staged for coalesced writes.
// ---------------------------------------------------------------------------
__global__ void pack_vt_kernel()
{
    __shared__ float sf[128][66];
    const int l0 = blockIdx.x * 64, kvh = blockIdx.y;
    const int tid = threadIdx.x;

    // phase 1: coalesced read (lanes over d)
    #pragma unroll
    for (int i = 0; i < 32; i++) {
        int idx = tid + i * 256;            // 0..8191
        int ll = idx >> 7, d = idx & 127;
        sf[d][ll] = g_qkv[(size_t)(l0 + ll) * QKVN + VOFF + kvh * HDIM + d];
    }
    __syncthreads();

    // phase 2: pack + coalesced write (lanes over kp)
    const int kp_l = tid & 31;              // 0..31
    #pragma unroll
    for (int i = 0; i < 16; i++) {
        int d = (tid >> 5) + i * 8;
        uint32_t hi, lo;
        pack_hilo(sf[d][2 * kp_l], sf[d][2 * kp_l + 1], hi, lo);
        size_t base = ((size_t)kvh * HDIM + d) * 2048 + (l0 >> 1) + kp_l;
        g_vtp[base] = hi;
        g_vtp[base + 1024] = lo;
    }
}

// ---------------------------------------------------------------------------
// Flash attention: bf16 hi/lo split mma; K/V loaded pre-packed via cp.async
// (K double-buffered, V pipelined against S-mma/softmax).
// ---------------------------------------------------------------------------
#define QW 68
#define VW 44                              // 44 mod 32 = 12 -> conflict-free frags; 176B rows (16B-aligned)
#define QHI_OFF 0
#define QLO_OFF (128 * QW)                 // 8704
#define KBUF_OFF 17408                     // K buf b: hi at +b*8704, lo at +b*8704+4352
#define VTH_OFF (KBUF_OFF + 2 * 8704)      // 34816
#define VTL_OFF (VTH_OFF + 128 * VW)       // 40448
#define ATT_SMEM_WORDS (VTL_OFF + 128 * VW)  // 46080
#define ATT_SMEM_BYTES (ATT_SMEM_WORDS * 4)  // 184320

__global__ __launch_bounds__(256, 1) void attn_kernel()
{
    extern __shared__ uint32_t sw[];

    const int qt = (int)gridDim.x - 1 - (int)blockIdx.x;
    const int h  = blockIdx.y;
    const int kvh = h >> 2;
    const int qoff = h * HDIM;
    const int qbase = qt * 128;

    const int tid = threadIdx.x;
    const int w = tid >> 5, lane = tid & 31;
    const int g = lane >> 2, cc = lane & 3;

    // ---- load + pack Q tile (once) ----
    #pragma unroll
    for (int i = 0; i < 16; i++) {
        int idx = tid + i * 256;
        int row = idx >> 5, c4 = idx & 31;
        float4 v = *(const float4*)&g_qkv[(size_t)(qbase + row) * QKVN + qoff + c4 * 4];
        uint32_t h0, l0, h1, l1;
        pack_hilo(v.x, v.y, h0, l0);
        pack_hilo(v.z, v.w, h1, l1);
        int wo = row * QW + c4 * 2;
        sw[QHI_OFF + wo] = h0; sw[QHI_OFF + wo + 1] = h1;
        sw[QLO_OFF + wo] = l0; sw[QLO_OFF + wo + 1] = l1;
    }

    // async loaders from pre-packed global
    auto load_k = [&](int kb, int buf) {
        const uint32_t* src0 = &g_kp[((size_t)kvh * LSEQ + kb) * 128];
        const int base = KBUF_OFF + buf * 8704;
        #pragma unroll
        for (int i = 0; i < 8; i++) {
            int idx = tid + i * 256;             // 0..2047
            int half = idx >> 10;                // 0 hi, 1 lo
            int r = (idx >> 4) & 63;
            int ch = idx & 15;
            int woff = base + half * 4352 + r * QW + ch * 4;
            CP_ASYNC16(smem_u32(sw + woff), src0 + (size_t)r * 128 + half * 64 + ch * 4);
        }
        CP_COMMIT();
    };
    auto load_v = [&](int kb) {
        const uint32_t* src0 = &g_vtp[(size_t)kvh * HDIM * 2048 + (kb >> 1)];
        #pragma unroll
        for (int i = 0; i < 8; i++) {
            int idx = tid + i * 256;             // 0..2047
            int half = idx >> 10;
            int d = (idx >> 3) & 127;
            int ch = idx & 7;
            int woff = (half ? VTL_OFF : VTH_OFF) + d * VW + ch * 4;
            CP_ASYNC16(smem_u32(sw + woff), src0 + (size_t)d * 2048 + half * 1024 + ch * 4);
        }
        CP_COMMIT();
    };

    float m0 = -1e30f, m1 = -1e30f, l0s = 0.f, l1s = 0.f;
    float o[16][4];
    #pragma unroll
    for (int j = 0; j < 16; j++)
        #pragma unroll
        for (int i = 0; i < 4; i++) o[j][i] = 0.f;

    const int r0 = qbase + w * 16 + g;
    const int r1 = r0 + 8;
    const float sl2e = ATT_SCALE * LOG2E;
    const int nkt = 2 * qt + 2;

    load_k(0, 0);   // prologue

    for (int kt = 0; kt < nkt; kt++) {
        const int kb = kt * 64;
        const int kbase = KBUF_OFF + (kt & 1) * 8704;

        __syncthreads();                    // prior iter's smem consumers done
        load_v(kb);                         // group: V(kt)
        const bool more = (kt + 1 < nkt);
        if (more) load_k(kb + 64, (kt + 1) & 1);   // group: K(kt+1)

        if (more) CP_WAIT(2); else CP_WAIT(1);     // K(kt) ready
        __syncthreads();

        // ---- S = Q @ K^T (bf16 3-term split) ----
        float s[8][4];
        #pragma unroll
        for (int j = 0; j < 8; j++)
            #pragma unroll
            for (int i = 0; i < 4; i++) s[j][i] = 0.f;

        #pragma unroll
        for (int kk = 0; kk < 8; kk++) {
            uint32_t ah[4], al[4];
            int ab = (w * 16 + g) * QW + kk * 8 + cc;
            ah[0] = sw[QHI_OFF + ab];              al[0] = sw[QLO_OFF + ab];
            ah[1] = sw[QHI_OFF + ab + 8 * QW];     al[1] = sw[QLO_OFF + ab + 8 * QW];
            ah[2] = sw[QHI_OFF + ab + 4];          al[2] = sw[QLO_OFF + ab + 4];
            ah[3] = sw[QHI_OFF + ab + 8 * QW + 4]; al[3] = sw[QLO_OFF + ab + 8 * QW + 4];
            #pragma unroll
            for (int j = 0; j < 8; j++) {
                uint32_t bh[2], bl[2];
                int bb = kbase + (j * 8 + g) * QW + kk * 8 + cc;
                bh[0] = sw[bb];        bh[1] = sw[bb + 4];
                bl[0] = sw[bb + 4352]; bl[1] = sw[bb + 4352 + 4];
                mma_bf16(s[j], ah, bh);
                mma_bf16(s[j], al, bh);
                mma_bf16(s[j], ah, bl);
            }
        }

        if (kt >= 2 * qt) {
            #pragma unroll
            for (int j = 0; j < 8; j++) {
                int colb = kb + j * 8 + 2 * cc;
                if (colb > r0)     s[j][0] = -1e30f;
                if (colb + 1 > r0) s[j][1] = -1e30f;
                if (colb > r1)     s[j][2] = -1e30f;
                if (colb + 1 > r1) s[j][3] = -1e30f;
            }
        }

        float mx0 = -1e30f, mx1 = -1e30f;
        #pragma unroll
        for (int j = 0; j < 8; j++) {
            mx0 = fmaxf(mx0, fmaxf(s[j][0], s[j][1]));
            mx1 = fmaxf(mx1, fmaxf(s[j][2], s[j][3]));
        }
        mx0 = fmaxf(mx0, __shfl_xor_sync(0xffffffffu, mx0, 1));
        mx0 = fmaxf(mx0, __shfl_xor_sync(0xffffffffu, mx0, 2));
        mx1 = fmaxf(mx1, __shfl_xor_sync(0xffffffffu, mx1, 1));
        mx1 = fmaxf(mx1, __shfl_xor_sync(0xffffffffu, mx1, 2));

        float mn0 = fmaxf(m0, mx0), mn1 = fmaxf(m1, mx1);
        float corr0 = exp2f((m0 - mn0) * sl2e);
        float corr1 = exp2f((m1 - mn1) * sl2e);
        m0 = mn0; m1 = mn1;

        uint32_t Ph0[8], Pl0[8], Ph1[8], Pl1[8];
        float sum0 = 0.f, sum1 = 0.f;
        #pragma unroll
        for (int j = 0; j < 8; j++) {
            float p0 = exp2f((s[j][0] - m0) * sl2e);
            float p1 = exp2f((s[j][1] - m0) * sl2e);
            float p2 = exp2f((s[j][2] - m1) * sl2e);
            float p3 = exp2f((s[j][3] - m1) * sl2e);
            sum0 += p0 + p1; sum1 += p2 + p3;
            pack_hilo(p0, p1, Ph0[j], Pl0[j]);
            pack_hilo(p2, p3, Ph1[j], Pl1[j]);
        }
        sum0 += __shfl_xor_sync(0xffffffffu, sum0, 1);
        sum0 += __shfl_xor_sync(0xffffffffu, sum0, 2);
        sum1 += __shfl_xor_sync(0xffffffffu, sum1, 1);
        sum1 += __shfl_xor_sync(0xffffffffu, sum1, 2);
        l0s = l0s * corr0 + sum0;
        l1s = l1s * corr1 + sum1;

        #pragma unroll
        for (int j = 0; j < 16; j++) {
            o[j][0] *= corr0; o[j][1] *= corr0;
            o[j][2] *= corr1; o[j][3] *= corr1;
        }

        if (more) CP_WAIT(1); else CP_WAIT(0);     // V(kt) ready
        __syncthreads();

        // ---- O += P @ V (bf16 3-term split) ----
        #pragma unroll
        for (int kk = 0; kk < 4; kk++) {
            uint32_t ah[4] = {Ph0[2 * kk], Ph1[2 * kk], Ph0[2 * kk + 1], Ph1[2 * kk + 1]};
            uint32_t al[4] = {Pl0[2 * kk], Pl1[2 * kk], Pl0[2 * kk + 1], Pl1[2 * kk + 1]};
            #pragma unroll
            for (int jn = 0; jn < 16; jn++) {
                uint32_t bh[2], bl[2];
                int vb = (jn * 8 + g) * VW + kk * 8 + cc;
                bh[0] = sw[VTH_OFF + vb]; bh[1] = sw[VTH_OFF + vb + 4];
                bl[0] = sw[VTL_OFF + vb]; bl[1] = sw[VTL_OFF + vb + 4];
                mma_bf16(o[jn], ah, bh);
                mma_bf16(o[jn], al, bh);
                mma_bf16(o[jn], ah, bl);
            }
        }
    }

    float li0 = 1.0f / l0s, li1 = 1.0f / l1s;
    #pragma unroll
    for (int jn = 0; jn < 16; jn++) {
        int col = h * HDIM + jn * 8 + 2 * cc;
        *(float2*)&g_o[(size_t)r0 * DMODEL + col] =
            make_float2(f32_to_tf32(o[jn][0] * li0), f32_to_tf32(o[jn][1] * li0));
        *(float2*)&g_o[(size_t)r1 * DMODEL + col] =
            make_float2(f32_to_tf32(o[jn][2] * li1), f32_to_tf32(o[jn][3] * li1));
    }
}

// ---------------------------------------------------------------------------
// Launch
// ---------------------------------------------------------------------------
extern "C" void kernel_launch(void* const* d_in, const int* in_sizes, int n_in,
                              void* d_out, int out_size)
{
    const float* x     = (const float*)d_in[0];
    const float* cosp  = (const float*)d_in[2];
    const float* sinp  = (const float*)d_in[3];
    const float* w_qkv = (const float*)d_in[4];
    const float* w_o   = (const float*)d_in[5];
    float* out = (float*)d_out;

    float *qkv_p, *o_p, *xr_p, *wqkvT_p, *woT_p;
    cudaGetSymbolAddress((void**)&qkv_p, g_qkv);
    cudaGetSymbolAddress((void**)&o_p, g_o);
    cudaGetSymbolAddress((void**)&xr_p, g_xr);
    cudaGetSymbolAddress((void**)&wqkvT_p, g_wqkvT);
    cudaGetSymbolAddress((void**)&woT_p, g_woT);

    cudaFuncSetAttribute(gemm_mma, cudaFuncAttributeMaxDynamicSharedMemorySize, GEMM_SMEM);
    cudaFuncSetAttribute(attn_kernel, cudaFuncAttributeMaxDynamicSharedMemorySize, ATT_SMEM_BYTES);

    // 0. tf32-round inputs / transpose weights to K-major
    rna_copy<<<(LSEQ * DMODEL / 4 + 255) / 256, 256>>>(x, xr_p, LSEQ * DMODEL / 4);
    transpose_rna<<<dim3(QKVN / 32, DMODEL / 32), dim3(32, 8)>>>(w_qkv, wqkvT_p, DMODEL, QKVN);
    transpose_rna<<<dim3(DMODEL / 32, DMODEL / 32), dim3(32, 8)>>>(w_o, woT_p, DMODEL, DMODEL);

    // 1. QKV projection (tf32 mma)
    gemm_mma<<<dim3(QKVN / BN, LSEQ / BM), 256, GEMM_SMEM>>>(xr_p, wqkvT_p, qkv_p, QKVN, DMODEL);

    // 2. RoPE
    rope_kernel<<<dim3(LSEQ, NH + NKV), 64>>>(cosp, sinp);

    // 3. Pack K / V^T to bf16 hi/lo once (shared across all attn CTAs)
    pack_k_kernel<<<dim3(LSEQ, NKV), 64>>>();
    pack_vt_kernel<<<dim3(LSEQ / 64, NKV), 256>>>();

    // 4. Flash attention (bf16 split mma; cp.async pipelined K/V)
    attn_kernel<<<dim3(LSEQ / 128, NH), 256, ATT_SMEM_BYTES>>>();

    // 5. Output projection (tf32 mma)
    gemm_mma<<<dim3(DMODEL / BN, LSEQ / BM), 256, GEMM_SMEM>>>(o_p, woT_p, out, DMODEL, DMODEL);
}

// round 8
// speedup vs baseline: 3.6047x; 1.0484x over previous
#include <cuda_runtime.h>
#include <cuda_bf16.h>
#include <math.h>
#include <stdint.h>

// Problem constants
#define LSEQ 2048
#define DMODEL 4096
#define NH 32
#define NKV 8
#define HDIM 128
#define QKVN 6144            // 32*128 + 2*8*128
#define KOFF 4096
#define VOFF 5120
#define ATT_SCALE 0.08838834764831843f
#define LOG2E 1.44269504089f

// Scratch (no cudaMalloc allowed)
__device__ float g_qkv[(size_t)LSEQ * QKVN];       // 50 MB
__device__ float g_o[(size_t)LSEQ * DMODEL];       // 33 MB
__device__ float g_xr[(size_t)LSEQ * DMODEL];      // 33 MB
__device__ float g_wqkvT[(size_t)QKVN * DMODEL];   // 100 MB
__device__ float g_woT[(size_t)DMODEL * DMODEL];   // 67 MB
// Packed bf16 hi/lo K and V^T (computed once post-RoPE, shared by all attn CTAs)
__device__ uint32_t g_kp[(size_t)NKV * LSEQ * 128];      // [kvh][l][hi 0..63 | lo 64..127]
__device__ uint32_t g_vtp[(size_t)NKV * HDIM * 2048];    // [kvh][d][hi kp 0..1023 | lo 1024..2047]

// ---------------------------------------------------------------------------
// Helpers
// ---------------------------------------------------------------------------
__device__ __forceinline__ uint32_t smem_u32(const void* p) {
    uint32_t a;
    asm("{ .reg .u64 t; cvta.to.shared.u64 t, %1; cvt.u32.u64 %0, t; }" : "=r"(a) : "l"(p));
    return a;
}
__device__ __forceinline__ float f32_to_tf32(float v) {
    uint32_t o;
    asm("cvt.rna.tf32.f32 %0, %1;" : "=r"(o) : "f"(v));
    return __uint_as_float(o);
}
#define CP_ASYNC16(dst, src) \
    asm volatile("cp.async.cg.shared.global [%0], [%1], 16;" :: "r"(dst), "l"(src))
#define CP_COMMIT() asm volatile("cp.async.commit_group;")
#define CP_WAIT(n)  asm volatile("cp.async.wait_group %0;" :: "n"(n))

#define LDSM_X4(r0, r1, r2, r3, addr) \
    asm volatile("ldmatrix.sync.aligned.m8n8.x4.shared.b16 {%0,%1,%2,%3}, [%4];" \
                 : "=r"(r0), "=r"(r1), "=r"(r2), "=r"(r3) : "r"(addr))

__device__ __forceinline__ void mma_tf32(float* d, const uint32_t* a, const uint32_t* b) {
    asm volatile(
        "mma.sync.aligned.m16n8k8.row.col.f32.tf32.tf32.f32 "
        "{%0,%1,%2,%3}, {%4,%5,%6,%7}, {%8,%9}, {%0,%1,%2,%3};"
        : "+f"(d[0]), "+f"(d[1]), "+f"(d[2]), "+f"(d[3])
        : "r"(a[0]), "r"(a[1]), "r"(a[2]), "r"(a[3]), "r"(b[0]), "r"(b[1]));
}
__device__ __forceinline__ void mma_bf16(float* d, const uint32_t* a, const uint32_t* b) {
    asm volatile(
        "mma.sync.aligned.m16n8k16.row.col.f32.bf16.bf16.f32 "
        "{%0,%1,%2,%3}, {%4,%5,%6,%7}, {%8,%9}, {%0,%1,%2,%3};"
        : "+f"(d[0]), "+f"(d[1]), "+f"(d[2]), "+f"(d[3])
        : "r"(a[0]), "r"(a[1]), "r"(a[2]), "r"(a[3]), "r"(b[0]), "r"(b[1]));
}

// Pack (v0, v1) into bf16x2 hi word and residual-lo word. v0 -> low half.
__device__ __forceinline__ void pack_hilo(float v0, float v1, uint32_t& hi, uint32_t& lo) {
    __nv_bfloat162 h2 = __floats2bfloat162_rn(v0, v1);
    uint32_t hw = *(uint32_t*)&h2;
    float h0 = __uint_as_float(hw << 16);
    float h1 = __uint_as_float(hw & 0xffff0000u);
    __nv_bfloat162 l2 = __floats2bfloat162_rn(v0 - h0, v1 - h1);
    hi = hw;
    lo = *(uint32_t*)&l2;
}

// ---------------------------------------------------------------------------
// mma.sync tf32 GEMM: C[M,N] = A[M,K] @ BT[N,K]^T  (both K-major, tf32-rounded)
// CTA 128x128, K-tile 32, 3-stage cp.async, 8 warps (warp tile 32x64),
// 2 CTAs/SM. Fragments loaded via ldmatrix.x4 (24 scalar LDS -> 6 LDSM/k-step).
// 144B row stride => 8-row ldmatrix phases hit banks base+16i mod 128: conflict-free.
// ---------------------------------------------------------------------------
#define BM 128
#define BN 128
#define BK 32
#define NSTG 3
#define PADW 36                        // 32 floats + 4 pad; 144B rows
#define ASTG (BM * PADW)
#define STGF (2 * BM * PADW)           // A + B per stage = 9216 floats
#define GEMM_SMEM (NSTG * STGF * 4)    // 110592 B

__global__ __launch_bounds__(256, 2) void gemm_mma(
    const float* __restrict__ A, const float* __restrict__ BT,
    float* __restrict__ C, int N, int K)
{
    extern __shared__ float sm[];
    const int tid = threadIdx.x;
    const int wid = tid >> 5, lane = tid & 31;
    const int wm = wid & 3, wn = wid >> 2;
    const int g = lane >> 2, c = lane & 3;
    const int bm = blockIdx.y * BM, bn = blockIdx.x * BN;
    const int NC = K / BK;

    // ldmatrix lane->address decomposition (mat = lane>>3, r8 = lane&7)
    const int mat = lane >> 3, r8 = lane & 7;
    // A: mat -> (row += (mat&1)*8, k += (mat>>1)*4)
    const int a_row_l = wm * 32 + (mat & 1) * 8 + r8;
    const int a_k_l   = (mat >> 1) * 4;
    // B: mat -> (n += (mat>>1)*8, k += (mat&1)*4)
    const int b_row_l = wn * 64 + (mat >> 1) * 8 + r8;
    const int b_k_l   = (mat & 1) * 4;

    float acc[2][8][4];
    #pragma unroll
    for (int mf = 0; mf < 2; mf++)
        #pragma unroll
        for (int nf = 0; nf < 8; nf++)
            #pragma unroll
            for (int i = 0; i < 4; i++) acc[mf][nf][i] = 0.f;

    auto load_stage = [&](int ct, int s) {
        float* base = sm + s * STGF;
        const int kt = ct * BK;
        #pragma unroll
        for (int h = 0; h < 4; h++) {
            int idx = tid + h * 256;            // 0..1023
            int row = idx >> 3, c8 = idx & 7;
            CP_ASYNC16(smem_u32(base + row * PADW + c8 * 4),
                       A + (size_t)(bm + row) * K + kt + c8 * 4);
        }
        #pragma unroll
        for (int h = 0; h < 4; h++) {
            int idx = tid + h * 256;
            int row = idx >> 3, c8 = idx & 7;
            CP_ASYNC16(smem_u32(base + ASTG + row * PADW + c8 * 4),
                       BT + (size_t)(bn + row) * K + kt + c8 * 4);
        }
        CP_COMMIT();
    };

    load_stage(0, 0);
    load_stage(1, 1);

    for (int ct = 0; ct < NC; ct++) {
        CP_WAIT(1);
        __syncthreads();
        if (ct + 2 < NC) load_stage(ct + 2, (ct + 2) % NSTG);
        else CP_COMMIT();

        const float* As = sm + (ct % NSTG) * STGF;
        const float* Bs = As + ASTG;
        const uint32_t a_base = smem_u32(As + a_row_l * PADW + a_k_l);
        const uint32_t b_base = smem_u32(Bs + b_row_l * PADW + b_k_l);

        #pragma unroll
        for (int kk = 0; kk < 4; kk++) {
            uint32_t af[2][4], bf[8][2];
            #pragma unroll
            for (int mf = 0; mf < 2; mf++)
                LDSM_X4(af[mf][0], af[mf][1], af[mf][2], af[mf][3],
                        a_base + (mf * 16 * PADW + kk * 8) * 4);
            #pragma unroll
            for (int np = 0; np < 4; np++)
                LDSM_X4(bf[2 * np][0], bf[2 * np][1], bf[2 * np + 1][0], bf[2 * np + 1][1],
                        b_base + (np * 16 * PADW + kk * 8) * 4);
            #pragma unroll
            for (int mf = 0; mf < 2; mf++)
                #pragma unroll
                for (int nf = 0; nf < 8; nf++)
                    mma_tf32(acc[mf][nf], af[mf], bf[nf]);
        }
    }

    #pragma unroll
    for (int mf = 0; mf < 2; mf++) {
        #pragma unroll
        for (int nf = 0; nf < 8; nf++) {
            int row = bm + wm * 32 + mf * 16 + g;
            int col = bn + wn * 64 + nf * 8 + 2 * c;
            *(float2*)&C[(size_t)row * N + col] = make_float2(acc[mf][nf][0], acc[mf][nf][1]);
            *(float2*)&C[(size_t)(row + 8) * N + col] = make_float2(acc[mf][nf][2], acc[mf][nf][3]);
        }
    }
}

// ---------------------------------------------------------------------------
// Transpose + tf32 round / elementwise round
// ---------------------------------------------------------------------------
__global__ void transpose_rna(const float* __restrict__ src, float* __restrict__ dst,
                              int R, int C)
{
    __shared__ float t[32][33];
    const int bx = blockIdx.x * 32, by = blockIdx.y * 32;
    const int x = threadIdx.x, y0 = threadIdx.y;
    #pragma unroll
    for (int i = 0; i < 4; i++) {
        int r = by + y0 + i * 8;
        t[y0 + i * 8][x] = f32_to_tf32(src[(size_t)r * C + bx + x]);
    }
    __syncthreads();
    #pragma unroll
    for (int i = 0; i < 4; i++) {
        int c = bx + y0 + i * 8;
        dst[(size_t)c * R + by + x] = t[x][y0 + i * 8];
    }
}

__global__ void rna_copy(const float* __restrict__ src, float* __restrict__ dst, int n4)
{
    int i = blockIdx.x * blockDim.x + threadIdx.x;
    if (i < n4) {
        float4 v = ((const float4*)src)[i];
        v.x = f32_to_tf32(v.x); v.y = f32_to_tf32(v.y);
        v.z = f32_to_tf32(v.z); v.w = f32_to_tf32(v.w);
        ((float4*)dst)[i] = v;
    }
}

// ---------------------------------------------------------------------------
// RoPE
// ---------------------------------------------------------------------------
__global__ void rope_kernel(const float* __restrict__ cosp,
                            const float* __restrict__ sinp)
{
    const int l = blockIdx.x;
    const int y = blockIdx.y;
    const int t = threadIdx.x;
    const int off = (y < NH) ? y * HDIM : KOFF + (y - NH) * HDIM;
    const size_t base = (size_t)l * QKVN + off;

    float v  = g_qkv[base + t];
    int pj   = (t < 32) ? t + 32 : t - 32;
    float pv = g_qkv[base + pj];
    float cc = cosp[l * 64 + t];
    float ss = sinp[l * 64 + t];
    float o = (t < 32) ? fmaf(v, cc, -pv * ss) : fmaf(v, cc, pv * ss);
    __syncthreads();
    g_qkv[base + t] = o;
}

// ---------------------------------------------------------------------------
// Pack K (post-RoPE) to bf16 hi/lo words: g_kp[kvh][l][hi j | lo 64+j]
// ---------------------------------------------------------------------------
__global__ void pack_k_kernel()
{
    const int l = blockIdx.x, kvh = blockIdx.y, j = threadIdx.x;
    const float* src = &g_qkv[(size_t)l * QKVN + KOFF + kvh * HDIM];
    uint32_t hi, lo;
    pack_hilo(src[2 * j], src[2 * j + 1], hi, lo);
    uint32_t* dst = &g_kp[((size_t)kvh * LSEQ + l) * 128];
    dst[j] = hi;
    dst[64 + j] = lo;
}

// ---------------------------------------------------------------------------
// Pack V transposed: g_vtp[kvh][d][hi kp | lo 1024+kp]
// ---------------------------------------------------------------------------
__global__ void pack_vt_kernel()
{
    __shared__ float sf[128][66];
    const int l0 = blockIdx.x * 64, kvh = blockIdx.y;
    const int tid = threadIdx.x;

    #pragma unroll
    for (int i = 0; i < 32; i++) {
        int idx = tid + i * 256;
        int ll = idx >> 7, d = idx & 127;
        sf[d][ll] = g_qkv[(size_t)(l0 + ll) * QKVN + VOFF + kvh * HDIM + d];
    }
    __syncthreads();

    const int kp_l = tid & 31;
    #pragma unroll
    for (int i = 0; i < 16; i++) {
        int d = (tid >> 5) + i * 8;
        uint32_t hi, lo;
        pack_hilo(sf[d][2 * kp_l], sf[d][2 * kp_l + 1], hi, lo);
        size_t base = ((size_t)kvh * HDIM + d) * 2048 + (l0 >> 1) + kp_l;
        g_vtp[base] = hi;
        g_vtp[base + 1024] = lo;
    }
}

// ---------------------------------------------------------------------------
// Flash attention: bf16 hi/lo split mma; K/V loaded pre-packed via cp.async.
// ---------------------------------------------------------------------------
#define QW 68
#define VW 44
#define QHI_OFF 0
#define QLO_OFF (128 * QW)
#define KBUF_OFF 17408
#define VTH_OFF (KBUF_OFF + 2 * 8704)
#define VTL_OFF (VTH_OFF + 128 * VW)
#define ATT_SMEM_WORDS (VTL_OFF + 128 * VW)
#define ATT_SMEM_BYTES (ATT_SMEM_WORDS * 4)

__global__ __launch_bounds__(256, 1) void attn_kernel()
{
    extern __shared__ uint32_t sw[];

    const int qt = (int)gridDim.x - 1 - (int)blockIdx.x;
    const int h  = blockIdx.y;
    const int kvh = h >> 2;
    const int qoff = h * HDIM;
    const int qbase = qt * 128;

    const int tid = threadIdx.x;
    const int w = tid >> 5, lane = tid & 31;
    const int g = lane >> 2, cc = lane & 3;

    #pragma unroll
    for (int i = 0; i < 16; i++) {
        int idx = tid + i * 256;
        int row = idx >> 5, c4 = idx & 31;
        float4 v = *(const float4*)&g_qkv[(size_t)(qbase + row) * QKVN + qoff + c4 * 4];
        uint32_t h0, l0, h1, l1;
        pack_hilo(v.x, v.y, h0, l0);
        pack_hilo(v.z, v.w, h1, l1);
        int wo = row * QW + c4 * 2;
        sw[QHI_OFF + wo] = h0; sw[QHI_OFF + wo + 1] = h1;
        sw[QLO_OFF + wo] = l0; sw[QLO_OFF + wo + 1] = l1;
    }

    auto load_k = [&](int kb, int buf) {
        const uint32_t* src0 = &g_kp[((size_t)kvh * LSEQ + kb) * 128];
        const int base = KBUF_OFF + buf * 8704;
        #pragma unroll
        for (int i = 0; i < 8; i++) {
            int idx = tid + i * 256;
            int half = idx >> 10;
            int r = (idx >> 4) & 63;
            int ch = idx & 15;
            int woff = base + half * 4352 + r * QW + ch * 4;
            CP_ASYNC16(smem_u32(sw + woff), src0 + (size_t)r * 128 + half * 64 + ch * 4);
        }
        CP_COMMIT();
    };
    auto load_v = [&](int kb) {
        const uint32_t* src0 = &g_vtp[(size_t)kvh * HDIM * 2048 + (kb >> 1)];
        #pragma unroll
        for (int i = 0; i < 8; i++) {
            int idx = tid + i * 256;
            int half = idx >> 10;
            int d = (idx >> 3) & 127;
            int ch = idx & 7;
            int woff = (half ? VTL_OFF : VTH_OFF) + d * VW + ch * 4;
            CP_ASYNC16(smem_u32(sw + woff), src0 + (size_t)d * 2048 + half * 1024 + ch * 4);
        }
        CP_COMMIT();
    };

    float m0 = -1e30f, m1 = -1e30f, l0s = 0.f, l1s = 0.f;
    float o[16][4];
    #pragma unroll
    for (int j = 0; j < 16; j++)
        #pragma unroll
        for (int i = 0; i < 4; i++) o[j][i] = 0.f;

    const int r0 = qbase + w * 16 + g;
    const int r1 = r0 + 8;
    const float sl2e = ATT_SCALE * LOG2E;
    const int nkt = 2 * qt + 2;

    load_k(0, 0);

    for (int kt = 0; kt < nkt; kt++) {
        const int kb = kt * 64;
        const int kbase = KBUF_OFF + (kt & 1) * 8704;

        __syncthreads();
        load_v(kb);
        const bool more = (kt + 1 < nkt);
        if (more) load_k(kb + 64, (kt + 1) & 1);

        if (more) CP_WAIT(2); else CP_WAIT(1);
        __syncthreads();

        float s[8][4];
        #pragma unroll
        for (int j = 0; j < 8; j++)
            #pragma unroll
            for (int i = 0; i < 4; i++) s[j][i] = 0.f;

        #pragma unroll
        for (int kk = 0; kk < 8; kk++) {
            uint32_t ah[4], al[4];
            int ab = (w * 16 + g) * QW + kk * 8 + cc;
            ah[0] = sw[QHI_OFF + ab];              al[0] = sw[QLO_OFF + ab];
            ah[1] = sw[QHI_OFF + ab + 8 * QW];     al[1] = sw[QLO_OFF + ab + 8 * QW];
            ah[2] = sw[QHI_OFF + ab + 4];          al[2] = sw[QLO_OFF + ab + 4];
            ah[3] = sw[QHI_OFF + ab + 8 * QW + 4]; al[3] = sw[QLO_OFF + ab + 8 * QW + 4];
            #pragma unroll
            for (int j = 0; j < 8; j++) {
                uint32_t bh[2], bl[2];
                int bb = kbase + (j * 8 + g) * QW + kk * 8 + cc;
                bh[0] = sw[bb];        bh[1] = sw[bb + 4];
                bl[0] = sw[bb + 4352]; bl[1] = sw[bb + 4352 + 4];
                mma_bf16(s[j], ah, bh);
                mma_bf16(s[j], al, bh);
                mma_bf16(s[j], ah, bl);
            }
        }

        if (kt >= 2 * qt) {
            #pragma unroll
            for (int j = 0; j < 8; j++) {
                int colb = kb + j * 8 + 2 * cc;
                if (colb > r0)     s[j][0] = -1e30f;
                if (colb + 1 > r0) s[j][1] = -1e30f;
                if (colb > r1)     s[j][2] = -1e30f;
                if (colb + 1 > r1) s[j][3] = -1e30f;
            }
        }

        float mx0 = -1e30f, mx1 = -1e30f;
        #pragma unroll
        for (int j = 0; j < 8; j++) {
            mx0 = fmaxf(mx0, fmaxf(s[j][0], s[j][1]));
            mx1 = fmaxf(mx1, fmaxf(s[j][2], s[j][3]));
        }
        mx0 = fmaxf(mx0, __shfl_xor_sync(0xffffffffu, mx0, 1));
        mx0 = fmaxf(mx0, __shfl_xor_sync(0xffffffffu, mx0, 2));
        mx1 = fmaxf(mx1, __shfl_xor_sync(0xffffffffu, mx1, 1));
        mx1 = fmaxf(mx1, __shfl_xor_sync(0xffffffffu, mx1, 2));

        float mn0 = fmaxf(m0, mx0), mn1 = fmaxf(m1, mx1);
        float corr0 = exp2f((m0 - mn0) * sl2e);
        float corr1 = exp2f((m1 - mn1) * sl2e);
        m0 = mn0; m1 = mn1;

        uint32_t Ph0[8], Pl0[8], Ph1[8], Pl1[8];
        float sum0 = 0.f, sum1 = 0.f;
        #pragma unroll
        for (int j = 0; j < 8; j++) {
            float p0 = exp2f((s[j][0] - m0) * sl2e);
            float p1 = exp2f((s[j][1] - m0) * sl2e);
            float p2 = exp2f((s[j][2] - m1) * sl2e);
            float p3 = exp2f((s[j][3] - m1) * sl2e);
            sum0 += p0 + p1; sum1 += p2 + p3;
            pack_hilo(p0, p1, Ph0[j], Pl0[j]);
            pack_hilo(p2, p3, Ph1[j], Pl1[j]);
        }
        sum0 += __shfl_xor_sync(0xffffffffu, sum0, 1);
        sum0 += __shfl_xor_sync(0xffffffffu, sum0, 2);
        sum1 += __shfl_xor_sync(0xffffffffu, sum1, 1);
        sum1 += __shfl_xor_sync(0xffffffffu, sum1, 2);
        l0s = l0s * corr0 + sum0;
        l1s = l1s * corr1 + sum1;

        #pragma unroll
        for (int j = 0; j < 16; j++) {
            o[j][0] *= corr0; o[j][1] *= corr0;
            o[j][2] *= corr1; o[j][3] *= corr1;
        }

        if (more) CP_WAIT(1); else CP_WAIT(0);
        __syncthreads();

        #pragma unroll
        for (int kk = 0; kk < 4; kk++) {
            uint32_t ah[4] = {Ph0[2 * kk], Ph1[2 * kk], Ph0[2 * kk + 1], Ph1[2 * kk + 1]};
            uint32_t al[4] = {Pl0[2 * kk], Pl1[2 * kk], Pl0[2 * kk + 1], Pl1[2 * kk + 1]};
            #pragma unroll
            for (int jn = 0; jn < 16; jn++) {
                uint32_t bh[2], bl[2];
                int vb = (jn * 8 + g) * VW + kk * 8 + cc;
                bh[0] = sw[VTH_OFF + vb]; bh[1] = sw[VTH_OFF + vb + 4];
                bl[0] = sw[VTL_OFF + vb]; bl[1] = sw[VTL_OFF + vb + 4];
                mma_bf16(o[jn], ah, bh);
                mma_bf16(o[jn], al, bh);
                mma_bf16(o[jn], ah, bl);
            }
        }
    }

    float li0 = 1.0f / l0s, li1 = 1.0f / l1s;
    #pragma unroll
    for (int jn = 0; jn < 16; jn++) {
        int col = h * HDIM + jn * 8 + 2 * cc;
        *(float2*)&g_o[(size_t)r0 * DMODEL + col] =
            make_float2(f32_to_tf32(o[jn][0] * li0), f32_to_tf32(o[jn][1] * li0));
        *(float2*)&g_o[(size_t)r1 * DMODEL + col] =
            make_float2(f32_to_tf32(o[jn][2] * li1), f32_to_tf32(o[jn][3] * li1));
    }
}

// ---------------------------------------------------------------------------
// Launch
// ---------------------------------------------------------------------------
extern "C" void kernel_launch(void* const* d_in, const int* in_sizes, int n_in,
                              void* d_out, int out_size)
{
    const float* x     = (const float*)d_in[0];
    const float* cosp  = (const float*)d_in[2];
    const float* sinp  = (const float*)d_in[3];
    const float* w_qkv = (const float*)d_in[4];
    const float* w_o   = (const float*)d_in[5];
    float* out = (float*)d_out;

    float *qkv_p, *o_p, *xr_p, *wqkvT_p, *woT_p;
    cudaGetSymbolAddress((void**)&qkv_p, g_qkv);
    cudaGetSymbolAddress((void**)&o_p, g_o);
    cudaGetSymbolAddress((void**)&xr_p, g_xr);
    cudaGetSymbolAddress((void**)&wqkvT_p, g_wqkvT);
    cudaGetSymbolAddress((void**)&woT_p, g_woT);

    cudaFuncSetAttribute(gemm_mma, cudaFuncAttributeMaxDynamicSharedMemorySize, GEMM_SMEM);
    cudaFuncSetAttribute(attn_kernel, cudaFuncAttributeMaxDynamicSharedMemorySize, ATT_SMEM_BYTES);

    // 0. tf32-round inputs / transpose weights to K-major
    rna_copy<<<(LSEQ * DMODEL / 4 + 255) / 256, 256>>>(x, xr_p, LSEQ * DMODEL / 4);
    transpose_rna<<<dim3(QKVN / 32, DMODEL / 32), dim3(32, 8)>>>(w_qkv, wqkvT_p, DMODEL, QKVN);
    transpose_rna<<<dim3(DMODEL / 32, DMODEL / 32), dim3(32, 8)>>>(w_o, woT_p, DMODEL, DMODEL);

    // 1. QKV projection (tf32 mma, ldmatrix frags)
    gemm_mma<<<dim3(QKVN / BN, LSEQ / BM), 256, GEMM_SMEM>>>(xr_p, wqkvT_p, qkv_p, QKVN, DMODEL);

    // 2. RoPE
    rope_kernel<<<dim3(LSEQ, NH + NKV), 64>>>(cosp, sinp);

    // 3. Pack K / V^T to bf16 hi/lo once
    pack_k_kernel<<<dim3(LSEQ, NKV), 64>>>();
    pack_vt_kernel<<<dim3(LSEQ / 64, NKV), 256>>>();

    // 4. Flash attention
    attn_kernel<<<dim3(LSEQ / 128, NH), 256, ATT_SMEM_BYTES>>>();

    // 5. Output projection (tf32 mma, ldmatrix frags)
    gemm_mma<<<dim3(DMODEL / BN, LSEQ / BM), 256, GEMM_SMEM>>>(o_p, woT_p, out, DMODEL, DMODEL);
}